// round 8
// baseline (speedup 1.0000x reference)
#include <cuda_runtime.h>
#include <cuda_bf16.h>
#include <cstdint>
#include <math.h>

#define NB 256
#define NS 32
#define NL 32
#define ND 256
#define NE 64
#define KBIG 768          // Bt columns: [Hi | Lo | Hi-dup(unused)]

// ===================== scratch (device globals; no runtime alloc) =====================
__device__ float g_enc[NB*NS*ND];            // enc[b,s,d]
__device__ float g_eW [NB*NS*ND];            // enc @ W
__device__ float g_kV [NB*NE*ND];            // keys @ V
__device__ int   g_act[NB*NS];
__device__ float g_dek[NB*NE*NS];            // dot(enc_s, keys_row), [row][s]
__device__ __nv_bfloat16 g_Ut[ND*KBIG];      // U^T  [Hi|Lo|Hi]
__device__ __nv_bfloat16 g_Vt[ND*KBIG];      // V^T  [Hi|Lo|Hi]
__device__ __nv_bfloat16 g_Wt[ND*KBIG];      // W^T  [Hi|Lo|Hi]
__device__ __nv_bfloat16 g_kyhi[NB*NE*ND];   // keys split
__device__ __nv_bfloat16 g_kylo[NB*NE*ND];
__device__ __nv_bfloat16 g_enhi[NB*NS*ND];   // enc split
__device__ __nv_bfloat16 g_enlo[NB*NS*ND];
__device__ __nv_bfloat16 g_hA_hi[NB*NE*ND];  // h split hi (row,k)
__device__ __nv_bfloat16 g_hA_lo[NB*NE*ND];  // h split lo

// ===================== PTX wrappers =====================
__device__ __forceinline__ uint32_t smem_u32(const void* p) {
    uint32_t a;
    asm("{ .reg .u64 t; cvta.to.shared.u64 t, %1; cvt.u32.u64 %0, t; }" : "=r"(a) : "l"(p));
    return a;
}
__device__ __forceinline__ void cpa16(uint32_t dst, const void* src) {
    asm volatile("cp.async.cg.shared.global [%0], [%1], 16;" :: "r"(dst), "l"(src));
}
#define CP_COMMIT() asm volatile("cp.async.commit_group;" ::: "memory")
#define CP_WAIT1()  asm volatile("cp.async.wait_group 1;"  ::: "memory")
#define CP_WAIT0()  asm volatile("cp.async.wait_group 0;"  ::: "memory")

__device__ __forceinline__ void ldsm_x4(uint32_t* r, uint32_t addr) {
    asm volatile("ldmatrix.sync.aligned.m8n8.x4.shared.b16 {%0,%1,%2,%3}, [%4];"
        : "=r"(r[0]), "=r"(r[1]), "=r"(r[2]), "=r"(r[3]) : "r"(addr));
}
__device__ __forceinline__ void ldsm_x2(uint32_t* r, uint32_t addr) {
    asm volatile("ldmatrix.sync.aligned.m8n8.x2.shared.b16 {%0,%1}, [%2];"
        : "=r"(r[0]), "=r"(r[1]) : "r"(addr));
}
__device__ __forceinline__ void mma_bf16(float* d, const uint32_t* a, const uint32_t* b) {
    asm volatile("mma.sync.aligned.m16n8k16.row.col.f32.bf16.bf16.f32 "
        "{%0,%1,%2,%3}, {%4,%5,%6,%7}, {%8,%9}, {%0,%1,%2,%3};"
        : "+f"(d[0]), "+f"(d[1]), "+f"(d[2]), "+f"(d[3])
        : "r"(a[0]), "r"(a[1]), "r"(a[2]), "r"(a[3]), "r"(b[0]), "r"(b[1]));
}

// ===================== steps smem layout (144B row stride, k64 chunks) ==============
#define SM_GATE 0
#define SM_RSQ  512
#define SM_DV   1024
#define SM_DH   1536
#define SM_GN   2048
#define SM_ACTS 2560
#define SM_ST0  4096
#define STG_BOF 0                           // B tile: 256 rows * 144B = 36864
#define STG_AHOF 36864                      // A-hi: 128 rows * 144B = 18432
#define STG_ALOF 55296                      // A-lo: 18432
#define STG     73728
#define SMEM_STEPS (SM_ST0 + 3*STG)         // 225280

// ===================== gemm0 smem layout (144B stride, k64 chunks) ==================
#define G_A_TILE 18432
#define G_B_TILE 36864
#define G_STAGE  55296
#define SMEM_G0  (3*G_STAGE)                // 165888

// ===================== encode (vectorized) =====================
__global__ __launch_bounds__(256)
void encode_kernel(const int* __restrict__ tok, const float* __restrict__ mask,
                   const float* __restrict__ emb) {
    __shared__ float4 red[4][64];
    const int bs = blockIdx.x, tid = threadIdx.x;
    const int lg = tid >> 6, d4 = tid & 63;
    const int*   t = tok  + (size_t)bs*NL;
    const float* m = mask + (size_t)bs*NL;

    if (tid < 32) {
        float mv = m[tid];
        #pragma unroll
        for (int o = 16; o > 0; o >>= 1) mv += __shfl_xor_sync(0xffffffffu, mv, o);
        if (tid == 0) g_act[bs] = (mv > 0.f) ? 1 : 0;
    }

    float4 acc = make_float4(0.f, 0.f, 0.f, 0.f);
    #pragma unroll
    for (int i = 0; i < 8; i++) {
        int l = lg*8 + i;
        float mv = __ldg(m + l);
        int   tv = __ldg(t + l);
        float4 e = __ldg((const float4*)(emb + (size_t)tv*ND) + d4);
        acc.x += mv*e.x; acc.y += mv*e.y; acc.z += mv*e.z; acc.w += mv*e.w;
    }
    red[lg][d4] = acc;
    __syncthreads();
    if (lg == 0) {
        float4 a = red[0][d4], b = red[1][d4], c = red[2][d4], d = red[3][d4];
        ((float4*)(g_enc + (size_t)bs*ND))[d4] =
            make_float4(a.x+b.x+c.x+d.x, a.y+b.y+c.y+d.y, a.z+b.z+c.z+d.z, a.w+b.w+c.w+d.w);
    }
}

// ===================== prep: Mt[n][k] = [Mhi^T | Mlo^T | Mhi^T] =====================
__global__ void prep_bt_all(const float* __restrict__ U, const float* __restrict__ V,
                            const float* __restrict__ W) {
    int n = blockIdx.x & 255, which = blockIdx.x >> 8, k = threadIdx.x;
    const float* M = (which == 0) ? U : (which == 1) ? V : W;
    __nv_bfloat16* out = (which == 0) ? g_Ut : (which == 1) ? g_Vt : g_Wt;
    float v = M[(size_t)k*ND + n];
    __nv_bfloat16 hi = __float2bfloat16(v);
    __nv_bfloat16 lo = __float2bfloat16(v - __bfloat162float(hi));
    out[(size_t)n*KBIG + k]       = hi;
    out[(size_t)n*KBIG + 256 + k] = lo;
    out[(size_t)n*KBIG + 512 + k] = hi;
}

// ===================== split fp32 -> bf16 hi/lo (keys and enc) =====================
__global__ void split_kernel(const float* __restrict__ keys) {
    int i = blockIdx.x * blockDim.x + threadIdx.x;
    const int NK = NB*NE*ND;
    float v; __nv_bfloat16 *ph, *pl; int idx;
    if (i < NK) { v = keys[i]; ph = g_kyhi; pl = g_kylo; idx = i; }
    else        { idx = i - NK; v = g_enc[idx]; ph = g_enhi; pl = g_enlo; }
    __nv_bfloat16 h = __float2bfloat16(v);
    ph[idx] = h;
    pl[idx] = __float2bfloat16(v - __bfloat162float(h));
}

// ===================== HMMA prelude GEMM: kV = keys@V and eW = enc@W ================
__global__ void __launch_bounds__(512, 1)
hmma_gemm0() {
    extern __shared__ char smem[];
    const uint32_t sb = smem_u32(smem);
    const int tid  = threadIdx.x;
    const int lane = tid & 31;
    const int wid  = tid >> 5;
    const int warp_m = wid >> 2, warp_n = wid & 3;
    const int bx = blockIdx.x;

    const __nv_bfloat16 *Ahi, *Alo, *Bt; float* C; int rowBase;
    if (bx < 128) { Ahi = g_kyhi; Alo = g_kylo; Bt = g_Vt; C = g_kV; rowBase = bx*128; }
    else          { Ahi = g_enhi; Alo = g_enlo; Bt = g_Wt; C = g_eW; rowBase = (bx-128)*128; }
    const __nv_bfloat16* hi = Ahi + (size_t)rowBase*ND;
    const __nv_bfloat16* lo = Alo + (size_t)rowBase*ND;

    const int selA = lane >> 3;
    const uint32_t aoff = (uint32_t)(((selA & 1)*8 + (lane & 7))*144 + (selA >> 1)*16);
    const int l16 = lane & 15;
    const uint32_t boff = (uint32_t)((l16 & 7)*144 + (l16 >> 3)*16);

    auto load_chunk = [&](int c, int slot) {
        const __nv_bfloat16* asrc = ((c < 8) ? hi : lo) + (c & 3)*64;
        const __nv_bfloat16* bsrc = Bt + c*64;
        uint32_t adst = sb + (uint32_t)slot*G_STAGE;
        uint32_t bdst = adst + G_A_TILE;
        #pragma unroll
        for (int i = 0; i < 2; i++) {
            int idx = tid + i*512, row = idx >> 3, seg = idx & 7;
            cpa16(adst + row*144 + seg*16, asrc + (size_t)row*ND + seg*8);
        }
        #pragma unroll
        for (int i = 0; i < 4; i++) {
            int idx = tid + i*512, n = idx >> 3, seg = idx & 7;
            cpa16(bdst + n*144 + seg*16, bsrc + (size_t)n*KBIG + seg*8);
        }
    };

    float acc[2][8][4];
    #pragma unroll
    for (int mt = 0; mt < 2; mt++)
        #pragma unroll
        for (int nt = 0; nt < 8; nt++)
            #pragma unroll
            for (int q = 0; q < 4; q++) acc[mt][nt][q] = 0.f;

    load_chunk(0, 0); CP_COMMIT();
    load_chunk(1, 1); CP_COMMIT();
    #pragma unroll
    for (int c = 0; c < 12; ++c) {
        if (c < 11) CP_WAIT1(); else CP_WAIT0();
        __syncthreads();
        if (c < 10) { load_chunk(c + 2, (c + 2) % 3); CP_COMMIT(); }
        const uint32_t base = sb + (uint32_t)(c % 3)*G_STAGE;
        const uint32_t abase = base + (warp_m*32)*144 + aoff;
        const uint32_t bbase = base + G_A_TILE + (warp_n*64)*144 + boff;
        #pragma unroll
        for (int k4 = 0; k4 < 4; ++k4) {
            const uint32_t kb = k4 * 32;
            uint32_t a0[4], a1[4];
            ldsm_x4(a0, abase + kb);
            ldsm_x4(a1, abase + 16*144 + kb);
            #pragma unroll
            for (int nt = 0; nt < 8; ++nt) {
                uint32_t bfrag[2];
                ldsm_x2(bfrag, bbase + nt*8*144 + kb);
                mma_bf16(acc[0][nt], a0, bfrag);
                mma_bf16(acc[1][nt], a1, bfrag);
            }
        }
        __syncthreads();
    }

    #pragma unroll
    for (int mt = 0; mt < 2; mt++) {
        int rA = warp_m*32 + mt*16 + (lane >> 2);
        int rB = rA + 8;
        size_t gOA = (size_t)(rowBase + rA)*ND;
        size_t gOB = (size_t)(rowBase + rB)*ND;
        #pragma unroll
        for (int nt = 0; nt < 8; nt++) {
            int col = warp_n*64 + nt*8 + 2*(lane & 3);
            *(float2*)(C + gOA + col) = make_float2(acc[mt][nt][0], acc[mt][nt][1]);
            *(float2*)(C + gOB + col) = make_float2(acc[mt][nt][2], acc[mt][nt][3]);
        }
    }
}

// ===================== persistent fused recurrence (k64 chunks, 8 barriers/step) =====
__global__ void __launch_bounds__(512, 1)
steps_kernel(const float* __restrict__ keys, float* __restrict__ h) {
    extern __shared__ char smem[];
    const uint32_t sb = smem_u32(smem);
    const int tid    = threadIdx.x;
    const int lane   = tid & 31;
    const int wid    = tid >> 5;
    const int warp_m = wid >> 2;          // 0..3 -> 32 rows
    const int warp_n = wid & 3;           // 0..3 -> 64 cols
    const int rowBase = blockIdx.x * 128;

    float* gs   = (float*)(smem + SM_GATE);
    float* rs   = (float*)(smem + SM_RSQ);
    float* dV   = (float*)(smem + SM_DV);
    float* dH   = (float*)(smem + SM_DH);
    float* gn   = (float*)(smem + SM_GN);
    int*   acts = (int*)  (smem + SM_ACTS);

    // ---------- phase 0: g_dek[row][s] = dot(enc_s, keys_row) once ----------
    {
        int r = tid >> 2, part = tid & 3;
        int grow = rowBase + r, b = grow >> 6;
        float4 ky[16];
        const float4* kp = (const float4*)(keys + (size_t)grow*ND + part*64);
        #pragma unroll
        for (int i = 0; i < 16; i++) ky[i] = kp[i];
        for (int s = 0; s < NS; s++) {
            const float4* ep = (const float4*)(g_enc + ((size_t)b*NS + s)*ND + part*64);
            float d = 0.f;
            #pragma unroll
            for (int i = 0; i < 16; i++) {
                float4 e = ep[i];
                d += ky[i].x*e.x + ky[i].y*e.y + ky[i].z*e.z + ky[i].w*e.w;
            }
            d += __shfl_xor_sync(0xffffffffu, d, 1);
            d += __shfl_xor_sync(0xffffffffu, d, 2);
            if (part == 0) g_dek[(size_t)grow*NS + s] = d;
        }
        if (tid < 128) gn[tid] = 0.f;
    }

    const __nv_bfloat16* hi = g_hA_hi + (size_t)rowBase*ND;
    const __nv_bfloat16* lo = g_hA_lo + (size_t)rowBase*ND;

    // ldmatrix per-lane offsets (144B row stride)
    const int selA = lane >> 3;
    const uint32_t aoff  = (uint32_t)(((selA & 1)*8 + (lane & 7))*144 + (selA >> 1)*16);
    const uint32_t boff4 = (uint32_t)(((lane >> 4)*8 + (lane & 7))*144 + ((lane >> 3) & 1)*16);

    float acc[2][8][4];

    // q 0..3: B = Hi[k64], A = hi+lo; q 4..7: B = Lo[k64], A = hi only
    auto load_chunk = [&](int q, int slot) {
        int kk = (q & 3) * 64;
        const __nv_bfloat16* bsrc = g_Ut + ((q < 4) ? kk : (256 + kk));
        uint32_t base = sb + SM_ST0 + (uint32_t)slot*STG;
        #pragma unroll
        for (int i = 0; i < 4; i++) {          // B: 256 rows x 8 segs of 16B
            int idx = tid + i*512, row = idx >> 3, seg = idx & 7;
            cpa16(base + row*144 + seg*16, bsrc + (size_t)row*KBIG + seg*8);
        }
        #pragma unroll
        for (int i = 0; i < 2; i++) {          // A hi: 128 rows x 8 segs
            int idx = tid + i*512, row = idx >> 3, seg = idx & 7;
            cpa16(base + STG_AHOF + row*144 + seg*16, hi + (size_t)row*ND + kk + seg*8);
        }
        if (q < 4) {
            #pragma unroll
            for (int i = 0; i < 2; i++) {      // A lo
                int idx = tid + i*512, row = idx >> 3, seg = idx & 7;
                cpa16(base + STG_ALOF + row*144 + seg*16, lo + (size_t)row*ND + kk + seg*8);
            }
        }
    };

    auto compute = [&](int q) {
        uint32_t base = sb + SM_ST0 + (uint32_t)(q % 3)*STG;
        uint32_t bB = base + (warp_n*64)*144 + boff4;
        uint32_t aH = base + STG_AHOF + (warp_m*32)*144 + aoff;
        uint32_t aL = base + STG_ALOF + (warp_m*32)*144 + aoff;
        #pragma unroll
        for (int k4 = 0; k4 < 4; ++k4) {
            const uint32_t kb = (uint32_t)k4 * 32;
            uint32_t bq[16];
            #pragma unroll
            for (int np = 0; np < 4; np++) ldsm_x4(&bq[np*4], bB + np*2304 + kb);
            uint32_t ah[8];
            ldsm_x4(ah,     aH + kb);
            ldsm_x4(ah + 4, aH + 16*144 + kb);
            #pragma unroll
            for (int np = 0; np < 4; np++) {
                mma_bf16(acc[0][2*np],   ah,     &bq[np*4]);
                mma_bf16(acc[0][2*np+1], ah,     &bq[np*4+2]);
                mma_bf16(acc[1][2*np],   ah + 4, &bq[np*4]);
                mma_bf16(acc[1][2*np+1], ah + 4, &bq[np*4+2]);
            }
            if (q < 4) {
                uint32_t al[8];
                ldsm_x4(al,     aL + kb);
                ldsm_x4(al + 4, aL + 16*144 + kb);
                #pragma unroll
                for (int np = 0; np < 4; np++) {
                    mma_bf16(acc[0][2*np],   al,     &bq[np*4]);
                    mma_bf16(acc[0][2*np+1], al,     &bq[np*4+2]);
                    mma_bf16(acc[1][2*np],   al + 4, &bq[np*4]);
                    mma_bf16(acc[1][2*np+1], al + 4, &bq[np*4+2]);
                }
            }
        }
    };

    for (int s = 0; s < NS; ++s) {
        const bool first = (s == 0);
        const bool last  = (s == NS - 1);
        __syncthreads();                  // prev pass2 / phase0 done
        if (tid < 128) {
            int grow = rowBase + tid;
            int b = grow >> 6;
            gs[tid]   = 1.f / (1.f + expf(-(gn[tid] + g_dek[(size_t)grow*NS + s])));
            acts[tid] = g_act[b*NS + s];
            rs[tid] = 0.f; dV[tid] = 0.f; dH[tid] = 0.f;
        }

        #pragma unroll
        for (int mt = 0; mt < 2; mt++)
            #pragma unroll
            for (int nt = 0; nt < 8; nt++)
                #pragma unroll
                for (int q = 0; q < 4; q++) acc[mt][nt][q] = 0.f;

        if (!first) {
            load_chunk(0, 0); CP_COMMIT();
            load_chunk(1, 1); CP_COMMIT();
            for (int q = 0; q < 8; ++q) {
                if (q < 7) CP_WAIT1(); else CP_WAIT0();
                __syncthreads();
                if (q < 6) { load_chunk(q + 2, (q + 2) % 3); CP_COMMIT(); }
                compute(q);
            }
        } else {
            __syncthreads();
        }

        // ---------- epilogue pass 1 ----------
        const int sn = (s + 1 < NS) ? s + 1 : NS - 1;
        #pragma unroll
        for (int mt = 0; mt < 2; mt++) {
            int rA = warp_m*32 + mt*16 + (lane >> 2);
            int rB = rA + 8;
            int gA = rowBase + rA, gB = rowBase + rB;
            int bA = gA >> 6;
            const float* kvA = g_kV + (size_t)gA*ND;
            const float* kvB = g_kV + (size_t)gB*ND;
            const float* ewR = g_eW  + ((size_t)bA*NS + s )*ND;
            const float* enN = g_enc + ((size_t)bA*NS + sn)*ND;
            float gateA = gs[rA], gateB = gs[rB];
            float sA = 0.f, sB = 0.f;
            float dVA = 0.f, dVB = 0.f, dHA = 0.f, dHB = 0.f;
            #pragma unroll
            for (int nt = 0; nt < 8; nt++) {
                int col = warp_n*64 + nt*8 + 2*(lane & 3);
                float2 en = *(const float2*)(enN + col);
                float2 ew = *(const float2*)(ewR + col);
                float2 kv, ho;
                kv = *(const float2*)(kvA + col);
                if (first) ho = make_float2(0.f, 0.f);
                else {
                    __nv_bfloat162 hb = *(const __nv_bfloat162*)(g_hA_hi + (size_t)gA*ND + col);
                    __nv_bfloat162 lb = *(const __nv_bfloat162*)(g_hA_lo + (size_t)gA*ND + col);
                    ho = make_float2(__bfloat162float(hb.x) + __bfloat162float(lb.x),
                                     __bfloat162float(hb.y) + __bfloat162float(lb.y));
                }
                float v0 = fmaxf(acc[mt][nt][0] + kv.x + ew.x, 0.f);
                float v1 = fmaxf(acc[mt][nt][1] + kv.y + ew.y, 0.f);
                float h0 = ho.x + gateA*v0, h1 = ho.y + gateA*v1;
                acc[mt][nt][0] = h0; acc[mt][nt][1] = h1;
                sA  += h0*h0 + h1*h1;
                dVA += en.x*h0 + en.y*h1;
                dHA += en.x*ho.x + en.y*ho.y;
                kv = *(const float2*)(kvB + col);
                if (first) ho = make_float2(0.f, 0.f);
                else {
                    __nv_bfloat162 hb = *(const __nv_bfloat162*)(g_hA_hi + (size_t)gB*ND + col);
                    __nv_bfloat162 lb = *(const __nv_bfloat162*)(g_hA_lo + (size_t)gB*ND + col);
                    ho = make_float2(__bfloat162float(hb.x) + __bfloat162float(lb.x),
                                     __bfloat162float(hb.y) + __bfloat162float(lb.y));
                }
                float w0 = fmaxf(acc[mt][nt][2] + kv.x + ew.x, 0.f);
                float w1 = fmaxf(acc[mt][nt][3] + kv.y + ew.y, 0.f);
                float h2 = ho.x + gateB*w0, h3 = ho.y + gateB*w1;
                acc[mt][nt][2] = h2; acc[mt][nt][3] = h3;
                sB  += h2*h2 + h3*h3;
                dVB += en.x*h2 + en.y*h3;
                dHB += en.x*ho.x + en.y*ho.y;
            }
            #pragma unroll
            for (int o = 1; o <= 2; o <<= 1) {
                sA  += __shfl_xor_sync(0xffffffffu, sA,  o);
                sB  += __shfl_xor_sync(0xffffffffu, sB,  o);
                dVA += __shfl_xor_sync(0xffffffffu, dVA, o);
                dVB += __shfl_xor_sync(0xffffffffu, dVB, o);
                dHA += __shfl_xor_sync(0xffffffffu, dHA, o);
                dHB += __shfl_xor_sync(0xffffffffu, dHB, o);
            }
            if ((lane & 3) == 0) {
                atomicAdd(&rs[rA], sA);  atomicAdd(&rs[rB], sB);
                atomicAdd(&dV[rA], dVA); atomicAdd(&dV[rB], dVB);
                atomicAdd(&dH[rA], dHA); atomicAdd(&dH[rB], dHB);
            }
        }
        __syncthreads();
        if (tid < 128) {
            float r = rsqrtf(fmaxf(rs[tid], 1e-12f));
            rs[tid] = r;
            gn[tid] = acts[tid] ? dV[tid]*r : dH[tid];
        }
        __syncthreads();

        // ---------- epilogue pass 2: normalize + write bf16 hi/lo (+h at last) -------
        #pragma unroll
        for (int mt = 0; mt < 2; mt++) {
            int rA = warp_m*32 + mt*16 + (lane >> 2);
            int rB = rA + 8;
            float rn2[2] = { rs[rA], rs[rB] };
            int   ac2[2] = { acts[rA], acts[rB] };
            size_t gO2[2] = { (size_t)(rowBase + rA)*ND, (size_t)(rowBase + rB)*ND };
            #pragma unroll
            for (int half = 0; half < 2; half++) {
                float rn = rn2[half]; int aa = ac2[half]; size_t gO = gO2[half];
                #pragma unroll
                for (int nt = 0; nt < 8; nt++) {
                    int col = warp_n*64 + nt*8 + 2*(lane & 3);
                    float a0 = acc[mt][nt][half*2], a1 = acc[mt][nt][half*2+1];
                    if (aa || first) {
                        float v0 = aa ? a0*rn : 0.f;
                        float v1 = aa ? a1*rn : 0.f;
                        __nv_bfloat16 h0 = __float2bfloat16(v0), h1 = __float2bfloat16(v1);
                        *(__nv_bfloat162*)(g_hA_hi + gO + col) = __nv_bfloat162(h0, h1);
                        *(__nv_bfloat162*)(g_hA_lo + gO + col) = __nv_bfloat162(
                            __float2bfloat16(v0 - __bfloat162float(h0)),
                            __float2bfloat16(v1 - __bfloat162float(h1)));
                        if (last) *(float2*)(h + gO + col) = make_float2(v0, v1);
                    } else if (last) {
                        __nv_bfloat162 hb = *(const __nv_bfloat162*)(g_hA_hi + gO + col);
                        __nv_bfloat162 lb = *(const __nv_bfloat162*)(g_hA_lo + gO + col);
                        *(float2*)(h + gO + col) = make_float2(
                            __bfloat162float(hb.x) + __bfloat162float(lb.x),
                            __bfloat162float(hb.y) + __bfloat162float(lb.y));
                    }
                }
            }
        }
    }
}

// ===================== launch =====================
extern "C" void kernel_launch(void* const* d_in, const int* in_sizes, int n_in,
                              void* d_out, int out_size) {
    const int*   tok  = (const int*)  d_in[0];
    const float* mask = (const float*)d_in[1];
    const float* keys = (const float*)d_in[2];
    const float* emb  = (const float*)d_in[3];
    const float* U    = (const float*)d_in[4];
    const float* V    = (const float*)d_in[5];
    const float* W    = (const float*)d_in[6];
    float* h = (float*)d_out;

    cudaFuncSetAttribute(steps_kernel, cudaFuncAttributeMaxDynamicSharedMemorySize, SMEM_STEPS);
    cudaFuncSetAttribute(hmma_gemm0,   cudaFuncAttributeMaxDynamicSharedMemorySize, SMEM_G0);

    encode_kernel<<<NB*NS, 256>>>(tok, mask, emb);
    prep_bt_all<<<3*ND, ND>>>(U, V, W);
    split_kernel<<<(NB*NE*ND + NB*NS*ND)/256, 256>>>(keys);
    hmma_gemm0<<<192, 512, SMEM_G0>>>();
    steps_kernel<<<128, 512, SMEM_STEPS>>>(keys, h);
}

// round 9
// speedup vs baseline: 1.3496x; 1.3496x over previous
#include <cuda_runtime.h>
#include <cuda_bf16.h>
#include <cstdint>
#include <math.h>

#define NB 256
#define NS 32
#define NL 32
#define ND 256
#define NE 64
#define KBIG 768          // Bt columns: [Hi | Lo | Hi-dup(unused)]

// ===================== scratch (device globals; no runtime alloc) =====================
__device__ float g_enc[NB*NS*ND];            // enc[b,s,d]
__device__ float g_eW [NB*NS*ND];            // enc @ W
__device__ float g_kV [NB*NE*ND];            // keys @ V
__device__ int   g_act[NB*NS];
__device__ float g_dek[NB*NE*NS];            // dot(enc_s, keys_row), [row][s]
__device__ __nv_bfloat16 g_Ut[ND*KBIG];      // U^T  [Hi|Lo|Hi]
__device__ __nv_bfloat16 g_Vt[ND*KBIG];      // V^T  [Hi|Lo|Hi]
__device__ __nv_bfloat16 g_Wt[ND*KBIG];      // W^T  [Hi|Lo|Hi]
__device__ __nv_bfloat16 g_kyhi[NB*NE*ND];   // keys split
__device__ __nv_bfloat16 g_kylo[NB*NE*ND];
__device__ __nv_bfloat16 g_enhi[NB*NS*ND];   // enc split
__device__ __nv_bfloat16 g_enlo[NB*NS*ND];

// ===================== PTX wrappers =====================
__device__ __forceinline__ uint32_t smem_u32(const void* p) {
    uint32_t a;
    asm("{ .reg .u64 t; cvta.to.shared.u64 t, %1; cvt.u32.u64 %0, t; }" : "=r"(a) : "l"(p));
    return a;
}
__device__ __forceinline__ void cpa16(uint32_t dst, const void* src) {
    asm volatile("cp.async.cg.shared.global [%0], [%1], 16;" :: "r"(dst), "l"(src));
}
#define CP_COMMIT() asm volatile("cp.async.commit_group;" ::: "memory")
#define CP_WAIT1()  asm volatile("cp.async.wait_group 1;"  ::: "memory")
#define CP_WAIT0()  asm volatile("cp.async.wait_group 0;"  ::: "memory")

__device__ __forceinline__ void ldsm_x4(uint32_t* r, uint32_t addr) {
    asm volatile("ldmatrix.sync.aligned.m8n8.x4.shared.b16 {%0,%1,%2,%3}, [%4];"
        : "=r"(r[0]), "=r"(r[1]), "=r"(r[2]), "=r"(r[3]) : "r"(addr));
}
__device__ __forceinline__ void mma_bf16(float* d, const uint32_t* a, const uint32_t* b) {
    asm volatile("mma.sync.aligned.m16n8k16.row.col.f32.bf16.bf16.f32 "
        "{%0,%1,%2,%3}, {%4,%5,%6,%7}, {%8,%9}, {%0,%1,%2,%3};"
        : "+f"(d[0]), "+f"(d[1]), "+f"(d[2]), "+f"(d[3])
        : "r"(a[0]), "r"(a[1]), "r"(a[2]), "r"(a[3]), "r"(b[0]), "r"(b[1]));
}

// ===================== steps smem layout ==============
// control [0,4096) | A-hi persistent 64KB (512B rows, xor-swizzled) | A-lo 64KB |
// B ring: 3 stages x 20480 (80B rows, k32 chunks)
#define SM_GATE 0
#define SM_RSQ  512
#define SM_DV   1024
#define SM_DH   1536
#define SM_GN   2048
#define SM_ACTS 2560
#define SM_AHI  4096
#define SM_ALO  (4096 + 65536)
#define SM_RING (4096 + 131072)
#define STG     20480
#define SMEM_STEPS (SM_RING + 3*STG)        // 196608

// ===================== gemm0 smem layout (144B stride, k64 chunks) ==================
#define G_A_TILE 18432
#define G_B_TILE 36864
#define G_STAGE  55296
#define SMEM_G0  (3*G_STAGE)                // 165888

// ===================== encode (vectorized) =====================
__global__ __launch_bounds__(256)
void encode_kernel(const int* __restrict__ tok, const float* __restrict__ mask,
                   const float* __restrict__ emb) {
    __shared__ float4 red[4][64];
    const int bs = blockIdx.x, tid = threadIdx.x;
    const int lg = tid >> 6, d4 = tid & 63;
    const int*   t = tok  + (size_t)bs*NL;
    const float* m = mask + (size_t)bs*NL;

    if (tid < 32) {
        float mv = m[tid];
        #pragma unroll
        for (int o = 16; o > 0; o >>= 1) mv += __shfl_xor_sync(0xffffffffu, mv, o);
        if (tid == 0) g_act[bs] = (mv > 0.f) ? 1 : 0;
    }

    float4 acc = make_float4(0.f, 0.f, 0.f, 0.f);
    #pragma unroll
    for (int i = 0; i < 8; i++) {
        int l = lg*8 + i;
        float mv = __ldg(m + l);
        int   tv = __ldg(t + l);
        float4 e = __ldg((const float4*)(emb + (size_t)tv*ND) + d4);
        acc.x += mv*e.x; acc.y += mv*e.y; acc.z += mv*e.z; acc.w += mv*e.w;
    }
    red[lg][d4] = acc;
    __syncthreads();
    if (lg == 0) {
        float4 a = red[0][d4], b = red[1][d4], c = red[2][d4], d = red[3][d4];
        ((float4*)(g_enc + (size_t)bs*ND))[d4] =
            make_float4(a.x+b.x+c.x+d.x, a.y+b.y+c.y+d.y, a.z+b.z+c.z+d.z, a.w+b.w+c.w+d.w);
    }
}

// ===================== prep: Mt[n][k] = [Mhi^T | Mlo^T | Mhi^T] =====================
__global__ void prep_bt_all(const float* __restrict__ U, const float* __restrict__ V,
                            const float* __restrict__ W) {
    int n = blockIdx.x & 255, which = blockIdx.x >> 8, k = threadIdx.x;
    const float* M = (which == 0) ? U : (which == 1) ? V : W;
    __nv_bfloat16* out = (which == 0) ? g_Ut : (which == 1) ? g_Vt : g_Wt;
    float v = M[(size_t)k*ND + n];
    __nv_bfloat16 hi = __float2bfloat16(v);
    __nv_bfloat16 lo = __float2bfloat16(v - __bfloat162float(hi));
    out[(size_t)n*KBIG + k]       = hi;
    out[(size_t)n*KBIG + 256 + k] = lo;
    out[(size_t)n*KBIG + 512 + k] = hi;
}

// ===================== split fp32 -> bf16 hi/lo (keys and enc) =====================
__global__ void split_kernel(const float* __restrict__ keys) {
    int i = blockIdx.x * blockDim.x + threadIdx.x;
    const int NK = NB*NE*ND;
    float v; __nv_bfloat16 *ph, *pl; int idx;
    if (i < NK) { v = keys[i]; ph = g_kyhi; pl = g_kylo; idx = i; }
    else        { idx = i - NK; v = g_enc[idx]; ph = g_enhi; pl = g_enlo; }
    __nv_bfloat16 h = __float2bfloat16(v);
    ph[idx] = h;
    pl[idx] = __float2bfloat16(v - __bfloat162float(h));
}

// ===================== HMMA prelude GEMM: kV = keys@V and eW = enc@W ================
__device__ __forceinline__ void ldsm_x2g(uint32_t* r, uint32_t addr) {
    asm volatile("ldmatrix.sync.aligned.m8n8.x2.shared.b16 {%0,%1}, [%2];"
        : "=r"(r[0]), "=r"(r[1]) : "r"(addr));
}

__global__ void __launch_bounds__(512, 1)
hmma_gemm0() {
    extern __shared__ char smem[];
    const uint32_t sb = smem_u32(smem);
    const int tid  = threadIdx.x;
    const int lane = tid & 31;
    const int wid  = tid >> 5;
    const int warp_m = wid >> 2, warp_n = wid & 3;
    const int bx = blockIdx.x;

    const __nv_bfloat16 *Ahi, *Alo, *Bt; float* C; int rowBase;
    if (bx < 128) { Ahi = g_kyhi; Alo = g_kylo; Bt = g_Vt; C = g_kV; rowBase = bx*128; }
    else          { Ahi = g_enhi; Alo = g_enlo; Bt = g_Wt; C = g_eW; rowBase = (bx-128)*128; }
    const __nv_bfloat16* hi = Ahi + (size_t)rowBase*ND;
    const __nv_bfloat16* lo = Alo + (size_t)rowBase*ND;

    const int selA = lane >> 3;
    const uint32_t aoff = (uint32_t)(((selA & 1)*8 + (lane & 7))*144 + (selA >> 1)*16);
    const int l16 = lane & 15;
    const uint32_t boff = (uint32_t)((l16 & 7)*144 + (l16 >> 3)*16);

    auto load_chunk = [&](int c, int slot) {
        const __nv_bfloat16* asrc = ((c < 8) ? hi : lo) + (c & 3)*64;
        const __nv_bfloat16* bsrc = Bt + c*64;
        uint32_t adst = sb + (uint32_t)slot*G_STAGE;
        uint32_t bdst = adst + G_A_TILE;
        #pragma unroll
        for (int i = 0; i < 2; i++) {
            int idx = tid + i*512, row = idx >> 3, seg = idx & 7;
            cpa16(adst + row*144 + seg*16, asrc + (size_t)row*ND + seg*8);
        }
        #pragma unroll
        for (int i = 0; i < 4; i++) {
            int idx = tid + i*512, n = idx >> 3, seg = idx & 7;
            cpa16(bdst + n*144 + seg*16, bsrc + (size_t)n*KBIG + seg*8);
        }
    };

    float acc[2][8][4];
    #pragma unroll
    for (int mt = 0; mt < 2; mt++)
        #pragma unroll
        for (int nt = 0; nt < 8; nt++)
            #pragma unroll
            for (int q = 0; q < 4; q++) acc[mt][nt][q] = 0.f;

    load_chunk(0, 0); CP_COMMIT();
    load_chunk(1, 1); CP_COMMIT();
    #pragma unroll
    for (int c = 0; c < 12; ++c) {
        if (c < 11) CP_WAIT1(); else CP_WAIT0();
        __syncthreads();
        if (c < 10) { load_chunk(c + 2, (c + 2) % 3); CP_COMMIT(); }
        const uint32_t base = sb + (uint32_t)(c % 3)*G_STAGE;
        const uint32_t abase = base + (warp_m*32)*144 + aoff;
        const uint32_t bbase = base + G_A_TILE + (warp_n*64)*144 + boff;
        #pragma unroll
        for (int k4 = 0; k4 < 4; ++k4) {
            const uint32_t kb = k4 * 32;
            uint32_t a0[4], a1[4];
            ldsm_x4(a0, abase + kb);
            ldsm_x4(a1, abase + 16*144 + kb);
            #pragma unroll
            for (int nt = 0; nt < 8; ++nt) {
                uint32_t bfrag[2];
                ldsm_x2g(bfrag, bbase + nt*8*144 + kb);
                mma_bf16(acc[0][nt], a0, bfrag);
                mma_bf16(acc[1][nt], a1, bfrag);
            }
        }
        __syncthreads();
    }

    #pragma unroll
    for (int mt = 0; mt < 2; mt++) {
        int rA = warp_m*32 + mt*16 + (lane >> 2);
        int rB = rA + 8;
        size_t gOA = (size_t)(rowBase + rA)*ND;
        size_t gOB = (size_t)(rowBase + rB)*ND;
        #pragma unroll
        for (int nt = 0; nt < 8; nt++) {
            int col = warp_n*64 + nt*8 + 2*(lane & 3);
            *(float2*)(C + gOA + col) = make_float2(acc[mt][nt][0], acc[mt][nt][1]);
            *(float2*)(C + gOB + col) = make_float2(acc[mt][nt][2], acc[mt][nt][3]);
        }
    }
}

// ===================== persistent fused recurrence: h state lives in SMEM ============
__global__ void __launch_bounds__(512, 1)
steps_kernel(const float* __restrict__ keys, float* __restrict__ h) {
    extern __shared__ char smem[];
    const uint32_t sb = smem_u32(smem);
    const int tid    = threadIdx.x;
    const int lane   = tid & 31;
    const int wid    = tid >> 5;
    const int warp_m = wid >> 2;          // 0..3 -> 32 rows
    const int warp_n = wid & 3;           // 0..3 -> 64 cols
    const int rowBase = blockIdx.x * 128;

    float* gs   = (float*)(smem + SM_GATE);
    float* rs   = (float*)(smem + SM_RSQ);
    float* dV   = (float*)(smem + SM_DV);
    float* dH   = (float*)(smem + SM_DH);
    float* gn   = (float*)(smem + SM_GN);
    int*   acts = (int*)  (smem + SM_ACTS);

    // ---------- phase 0: g_dek[row][s] = dot(enc_s, keys_row) once ----------
    {
        int r = tid >> 2, part = tid & 3;
        int grow = rowBase + r, b = grow >> 6;
        float4 ky[16];
        const float4* kp = (const float4*)(keys + (size_t)grow*ND + part*64);
        #pragma unroll
        for (int i = 0; i < 16; i++) ky[i] = kp[i];
        for (int s = 0; s < NS; s++) {
            const float4* ep = (const float4*)(g_enc + ((size_t)b*NS + s)*ND + part*64);
            float d = 0.f;
            #pragma unroll
            for (int i = 0; i < 16; i++) {
                float4 e = ep[i];
                d += ky[i].x*e.x + ky[i].y*e.y + ky[i].z*e.z + ky[i].w*e.w;
            }
            d += __shfl_xor_sync(0xffffffffu, d, 1);
            d += __shfl_xor_sync(0xffffffffu, d, 2);
            if (part == 0) g_dek[(size_t)grow*NS + s] = d;
        }
        if (tid < 128) gn[tid] = 0.f;
    }

    // ---- per-lane constants ----
    // mainloop A (persistent, 512B rows, seg xor-swizzled by row&7)
    const int lane7 = lane & 7;
    const int sel2  = lane >> 4;                         // k16-half select
    const uint32_t arow = (uint32_t)(warp_m*32 + ((lane >> 3) & 1)*8 + lane7) * 512;
    // B ring (80B rows)
    const uint32_t boff4 = (uint32_t)(((lane >> 4)*8 + lane7)*80 + ((lane >> 3) & 1)*16);
    // epilogue smem A addressing
    const int r7 = (lane >> 2) & 7;                      // row&7 for rA/rB
    const uint32_t ebyte = (uint32_t)((lane & 3)*4);

    float acc[2][8][4];

    // q 0..7: B = Hi[k32] (A hi+lo sweeps); q 8..15: B = Lo[k32] (A hi only)
    auto load_chunk = [&](int q, int slot) {
        int kk = (q & 7) * 32;
        const __nv_bfloat16* bsrc = g_Ut + ((q < 8) ? kk : (256 + kk));
        uint32_t base = sb + SM_RING + (uint32_t)slot*STG;
        #pragma unroll
        for (int i = 0; i < 2; i++) {          // B: 256 rows x 4 segs of 16B
            int idx = tid + i*512, row = idx >> 2, seg = idx & 3;
            cpa16(base + row*80 + seg*16, bsrc + (size_t)row*KBIG + seg*8);
        }
    };

    auto compute = [&](int q) {
        uint32_t bB = sb + SM_RING + (uint32_t)(q % 3)*STG + (warp_n*64)*80 + boff4;
        const int kseg0 = (q & 7)*4 + sel2;    // 16B-seg index base within A row
        #pragma unroll
        for (int k2 = 0; k2 < 2; ++k2) {
            const uint32_t kb = (uint32_t)k2*32;
            uint32_t bq[16];
            #pragma unroll
            for (int np = 0; np < 4; np++) ldsm_x4(&bq[np*4], bB + np*1280 + kb);
            const uint32_t seg = (uint32_t)((kseg0 + k2*2) ^ lane7) * 16;
            uint32_t aHa = sb + SM_AHI + arow + seg;
            uint32_t ah[8];
            ldsm_x4(ah,     aHa);
            ldsm_x4(ah + 4, aHa + 8192);       // +16 rows * 512B
            #pragma unroll
            for (int np = 0; np < 4; np++) {
                mma_bf16(acc[0][2*np],   ah,     &bq[np*4]);
                mma_bf16(acc[0][2*np+1], ah,     &bq[np*4+2]);
                mma_bf16(acc[1][2*np],   ah + 4, &bq[np*4]);
                mma_bf16(acc[1][2*np+1], ah + 4, &bq[np*4+2]);
            }
            if (q < 8) {
                uint32_t aLa = sb + SM_ALO + arow + seg;
                uint32_t al[8];
                ldsm_x4(al,     aLa);
                ldsm_x4(al + 4, aLa + 8192);
                #pragma unroll
                for (int np = 0; np < 4; np++) {
                    mma_bf16(acc[0][2*np],   al,     &bq[np*4]);
                    mma_bf16(acc[0][2*np+1], al,     &bq[np*4+2]);
                    mma_bf16(acc[1][2*np],   al + 4, &bq[np*4]);
                    mma_bf16(acc[1][2*np+1], al + 4, &bq[np*4+2]);
                }
            }
        }
    };

    for (int s = 0; s < NS; ++s) {
        const bool first = (s == 0);
        const bool last  = (s == NS - 1);
        __syncthreads();                  // prev pass2 smem writes / phase0 done
        if (tid < 128) {
            int grow = rowBase + tid;
            int b = grow >> 6;
            gs[tid]   = 1.f / (1.f + expf(-(gn[tid] + g_dek[(size_t)grow*NS + s])));
            acts[tid] = g_act[b*NS + s];
            rs[tid] = 0.f; dV[tid] = 0.f; dH[tid] = 0.f;
        }

        #pragma unroll
        for (int mt = 0; mt < 2; mt++)
            #pragma unroll
            for (int nt = 0; nt < 8; nt++)
                #pragma unroll
                for (int q = 0; q < 4; q++) acc[mt][nt][q] = 0.f;

        if (!first) {
            load_chunk(0, 0); CP_COMMIT();
            load_chunk(1, 1); CP_COMMIT();
            for (int q = 0; q < 16; ++q) {
                if (q < 15) CP_WAIT1(); else CP_WAIT0();
                __syncthreads();
                if (q < 14) { load_chunk(q + 2, (q + 2) % 3); CP_COMMIT(); }
                compute(q);
            }
        } else {
            __syncthreads();
        }

        // ---------- epilogue pass 1 (h state read from persistent smem) ----------
        const int sn = (s + 1 < NS) ? s + 1 : NS - 1;
        #pragma unroll
        for (int mt = 0; mt < 2; mt++) {
            int rA = warp_m*32 + mt*16 + (lane >> 2);
            int rB = rA + 8;
            int gA = rowBase + rA, gB = rowBase + rB;
            int bA = gA >> 6;
            const float* kvA = g_kV + (size_t)gA*ND;
            const float* kvB = g_kV + (size_t)gB*ND;
            const float* ewR = g_eW  + ((size_t)bA*NS + s )*ND;
            const float* enN = g_enc + ((size_t)bA*NS + sn)*ND;
            float gateA = gs[rA], gateB = gs[rB];
            float sA = 0.f, sB = 0.f;
            float dVA = 0.f, dVB = 0.f, dHA = 0.f, dHB = 0.f;
            #pragma unroll
            for (int nt = 0; nt < 8; nt++) {
                int col = warp_n*64 + nt*8 + 2*(lane & 3);
                const uint32_t seg = (uint32_t)((warp_n*8 + nt) ^ r7) * 16;
                float2 en = *(const float2*)(enN + col);
                float2 ew = *(const float2*)(ewR + col);
                float2 kv, ho;
                kv = *(const float2*)(kvA + col);
                if (first) ho = make_float2(0.f, 0.f);
                else {
                    uint32_t offA = (uint32_t)rA*512 + seg + ebyte;
                    __nv_bfloat162 hb = *(__nv_bfloat162*)(smem + SM_AHI + offA);
                    __nv_bfloat162 lb = *(__nv_bfloat162*)(smem + SM_ALO + offA);
                    ho = make_float2(__bfloat162float(hb.x) + __bfloat162float(lb.x),
                                     __bfloat162float(hb.y) + __bfloat162float(lb.y));
                }
                float v0 = fmaxf(acc[mt][nt][0] + kv.x + ew.x, 0.f);
                float v1 = fmaxf(acc[mt][nt][1] + kv.y + ew.y, 0.f);
                float h0 = ho.x + gateA*v0, h1 = ho.y + gateA*v1;
                acc[mt][nt][0] = h0; acc[mt][nt][1] = h1;
                sA  += h0*h0 + h1*h1;
                dVA += en.x*h0 + en.y*h1;
                dHA += en.x*ho.x + en.y*ho.y;
                kv = *(const float2*)(kvB + col);
                if (first) ho = make_float2(0.f, 0.f);
                else {
                    uint32_t offB = (uint32_t)rB*512 + seg + ebyte;
                    __nv_bfloat162 hb = *(__nv_bfloat162*)(smem + SM_AHI + offB);
                    __nv_bfloat162 lb = *(__nv_bfloat162*)(smem + SM_ALO + offB);
                    ho = make_float2(__bfloat162float(hb.x) + __bfloat162float(lb.x),
                                     __bfloat162float(hb.y) + __bfloat162float(lb.y));
                }
                float w0 = fmaxf(acc[mt][nt][2] + kv.x + ew.x, 0.f);
                float w1 = fmaxf(acc[mt][nt][3] + kv.y + ew.y, 0.f);
                float h2 = ho.x + gateB*w0, h3 = ho.y + gateB*w1;
                acc[mt][nt][2] = h2; acc[mt][nt][3] = h3;
                sB  += h2*h2 + h3*h3;
                dVB += en.x*h2 + en.y*h3;
                dHB += en.x*ho.x + en.y*ho.y;
            }
            #pragma unroll
            for (int o = 1; o <= 2; o <<= 1) {
                sA  += __shfl_xor_sync(0xffffffffu, sA,  o);
                sB  += __shfl_xor_sync(0xffffffffu, sB,  o);
                dVA += __shfl_xor_sync(0xffffffffu, dVA, o);
                dVB += __shfl_xor_sync(0xffffffffu, dVB, o);
                dHA += __shfl_xor_sync(0xffffffffu, dHA, o);
                dHB += __shfl_xor_sync(0xffffffffu, dHB, o);
            }
            if ((lane & 3) == 0) {
                atomicAdd(&rs[rA], sA);  atomicAdd(&rs[rB], sB);
                atomicAdd(&dV[rA], dVA); atomicAdd(&dV[rB], dVB);
                atomicAdd(&dH[rA], dHA); atomicAdd(&dH[rB], dHB);
            }
        }
        __syncthreads();
        if (tid < 128) {
            float r = rsqrtf(fmaxf(rs[tid], 1e-12f));
            rs[tid] = r;
            gn[tid] = acts[tid] ? dV[tid]*r : dH[tid];
        }
        __syncthreads();

        // ---------- epilogue pass 2: normalize + write smem hi/lo (+h gmem at last) --
        #pragma unroll
        for (int mt = 0; mt < 2; mt++) {
            int rA = warp_m*32 + mt*16 + (lane >> 2);
            int rB = rA + 8;
            float rn2[2] = { rs[rA], rs[rB] };
            int   ac2[2] = { acts[rA], acts[rB] };
            int   rr2[2] = { rA, rB };
            #pragma unroll
            for (int half = 0; half < 2; half++) {
                float rn = rn2[half]; int aa = ac2[half]; int row = rr2[half];
                size_t gO = (size_t)(rowBase + row)*ND;
                #pragma unroll
                for (int nt = 0; nt < 8; nt++) {
                    int col = warp_n*64 + nt*8 + 2*(lane & 3);
                    uint32_t off = (uint32_t)row*512 + (uint32_t)((warp_n*8 + nt) ^ r7)*16 + ebyte;
                    float a0 = acc[mt][nt][half*2], a1 = acc[mt][nt][half*2+1];
                    if (aa || first) {
                        float v0 = aa ? a0*rn : 0.f;
                        float v1 = aa ? a1*rn : 0.f;
                        __nv_bfloat16 h0 = __float2bfloat16(v0), h1 = __float2bfloat16(v1);
                        *(__nv_bfloat162*)(smem + SM_AHI + off) = __nv_bfloat162(h0, h1);
                        *(__nv_bfloat162*)(smem + SM_ALO + off) = __nv_bfloat162(
                            __float2bfloat16(v0 - __bfloat162float(h0)),
                            __float2bfloat16(v1 - __bfloat162float(h1)));
                        if (last) *(float2*)(h + gO + col) = make_float2(v0, v1);
                    } else if (last) {
                        __nv_bfloat162 hb = *(__nv_bfloat162*)(smem + SM_AHI + off);
                        __nv_bfloat162 lb = *(__nv_bfloat162*)(smem + SM_ALO + off);
                        *(float2*)(h + gO + col) = make_float2(
                            __bfloat162float(hb.x) + __bfloat162float(lb.x),
                            __bfloat162float(hb.y) + __bfloat162float(lb.y));
                    }
                }
            }
        }
    }
}

// ===================== launch =====================
extern "C" void kernel_launch(void* const* d_in, const int* in_sizes, int n_in,
                              void* d_out, int out_size) {
    const int*   tok  = (const int*)  d_in[0];
    const float* mask = (const float*)d_in[1];
    const float* keys = (const float*)d_in[2];
    const float* emb  = (const float*)d_in[3];
    const float* U    = (const float*)d_in[4];
    const float* V    = (const float*)d_in[5];
    const float* W    = (const float*)d_in[6];
    float* h = (float*)d_out;

    cudaFuncSetAttribute(steps_kernel, cudaFuncAttributeMaxDynamicSharedMemorySize, SMEM_STEPS);
    cudaFuncSetAttribute(hmma_gemm0,   cudaFuncAttributeMaxDynamicSharedMemorySize, SMEM_G0);

    encode_kernel<<<NB*NS, 256>>>(tok, mask, emb);
    prep_bt_all<<<3*ND, ND>>>(U, V, W);
    split_kernel<<<(NB*NE*ND + NB*NS*ND)/256, 256>>>(keys);
    hmma_gemm0<<<192, 512, SMEM_G0>>>();
    steps_kernel<<<128, 512, SMEM_STEPS>>>(keys, h);
}

// round 10
// speedup vs baseline: 1.3815x; 1.0237x over previous
#include <cuda_runtime.h>
#include <cuda_bf16.h>
#include <cstdint>
#include <math.h>

#define NB 256
#define NS 32
#define NL 32
#define ND 256
#define NE 64
#define KBIG 768          // Bt columns: [Hi | Lo | Hi-dup(unused)]

// ===================== scratch (device globals; no runtime alloc) =====================
__device__ float g_enc[NB*NS*ND];            // enc[b,s,d]
__device__ float g_eW [NB*NS*ND];            // enc @ W
__device__ float g_kV [NB*NE*ND];            // keys @ V
__device__ int   g_act[NB*NS];
__device__ float g_dek[NB*NE*NS];            // dot(enc_s, keys_row), [row][s]
__device__ __nv_bfloat16 g_Ut[ND*KBIG];      // U^T  [Hi|Lo|Hi]
__device__ __nv_bfloat16 g_Vt[ND*KBIG];      // V^T  [Hi|Lo|Hi]
__device__ __nv_bfloat16 g_Wt[ND*KBIG];      // W^T  [Hi|Lo|Hi]
__device__ __nv_bfloat16 g_kyhi[NB*NE*ND];   // keys split
__device__ __nv_bfloat16 g_kylo[NB*NE*ND];
__device__ __nv_bfloat16 g_enhi[NB*NS*ND];   // enc split
__device__ __nv_bfloat16 g_enlo[NB*NS*ND];

// ===================== PTX wrappers =====================
__device__ __forceinline__ uint32_t smem_u32(const void* p) {
    uint32_t a;
    asm("{ .reg .u64 t; cvta.to.shared.u64 t, %1; cvt.u32.u64 %0, t; }" : "=r"(a) : "l"(p));
    return a;
}
__device__ __forceinline__ void cpa16(uint32_t dst, const void* src) {
    asm volatile("cp.async.cg.shared.global [%0], [%1], 16;" :: "r"(dst), "l"(src));
}
#define CP_COMMIT() asm volatile("cp.async.commit_group;" ::: "memory")
#define CP_WAIT2()  asm volatile("cp.async.wait_group 2;"  ::: "memory")
#define CP_WAIT1()  asm volatile("cp.async.wait_group 1;"  ::: "memory")
#define CP_WAIT0()  asm volatile("cp.async.wait_group 0;"  ::: "memory")

__device__ __forceinline__ void ldsm_x4(uint32_t* r, uint32_t addr) {
    asm volatile("ldmatrix.sync.aligned.m8n8.x4.shared.b16 {%0,%1,%2,%3}, [%4];"
        : "=r"(r[0]), "=r"(r[1]), "=r"(r[2]), "=r"(r[3]) : "r"(addr));
}
__device__ __forceinline__ void mma_bf16(float* d, const uint32_t* a, const uint32_t* b) {
    asm volatile("mma.sync.aligned.m16n8k16.row.col.f32.bf16.bf16.f32 "
        "{%0,%1,%2,%3}, {%4,%5,%6,%7}, {%8,%9}, {%0,%1,%2,%3};"
        : "+f"(d[0]), "+f"(d[1]), "+f"(d[2]), "+f"(d[3])
        : "r"(a[0]), "r"(a[1]), "r"(a[2]), "r"(a[3]), "r"(b[0]), "r"(b[1]));
}

// ===================== steps smem layout ==============
// control [0,4096) | A-hi persistent 64KB (512B rows, xor-swizzled) | A-lo 64KB |
// B ring: 4 stages x 20480 (80B rows, k32 chunks), continuous across steps
#define SM_GATE 0
#define SM_RSQ  512
#define SM_DV   1024
#define SM_DH   1536
#define SM_GN   2048
#define SM_ACTS 2560
#define SM_AHI  4096
#define SM_ALO  (4096 + 65536)
#define SM_RING (4096 + 131072)
#define STG     20480
#define SMEM_STEPS (SM_RING + 4*STG)        // 217088

// ===================== gemm0 smem layout (144B stride, k64 chunks) ==================
#define G_A_TILE 18432
#define G_B_TILE 36864
#define G_STAGE  55296
#define SMEM_G0  (3*G_STAGE)                // 165888

// ===================== encode (vectorized, + bf16 split fold-in) =====================
__global__ __launch_bounds__(256)
void encode_kernel(const int* __restrict__ tok, const float* __restrict__ mask,
                   const float* __restrict__ emb) {
    __shared__ float4 red[4][64];
    const int bs = blockIdx.x, tid = threadIdx.x;
    const int lg = tid >> 6, d4 = tid & 63;
    const int*   t = tok  + (size_t)bs*NL;
    const float* m = mask + (size_t)bs*NL;

    if (tid < 32) {
        float mv = m[tid];
        #pragma unroll
        for (int o = 16; o > 0; o >>= 1) mv += __shfl_xor_sync(0xffffffffu, mv, o);
        if (tid == 0) g_act[bs] = (mv > 0.f) ? 1 : 0;
    }

    float4 acc = make_float4(0.f, 0.f, 0.f, 0.f);
    #pragma unroll
    for (int i = 0; i < 8; i++) {
        int l = lg*8 + i;
        float mv = __ldg(m + l);
        int   tv = __ldg(t + l);
        float4 e = __ldg((const float4*)(emb + (size_t)tv*ND) + d4);
        acc.x += mv*e.x; acc.y += mv*e.y; acc.z += mv*e.z; acc.w += mv*e.w;
    }
    red[lg][d4] = acc;
    __syncthreads();
    if (lg == 0) {
        float4 a = red[0][d4], b = red[1][d4], c = red[2][d4], d = red[3][d4];
        float4 v = make_float4(a.x+b.x+c.x+d.x, a.y+b.y+c.y+d.y,
                               a.z+b.z+c.z+d.z, a.w+b.w+c.w+d.w);
        size_t off = (size_t)bs*ND + d4*4;
        *(float4*)(g_enc + off) = v;
        float vv[4] = {v.x, v.y, v.z, v.w};
        __nv_bfloat16 hb[4], lb[4];
        #pragma unroll
        for (int i = 0; i < 4; i++) {
            hb[i] = __float2bfloat16(vv[i]);
            lb[i] = __float2bfloat16(vv[i] - __bfloat162float(hb[i]));
        }
        *(__nv_bfloat162*)(g_enhi + off)     = __nv_bfloat162(hb[0], hb[1]);
        *(__nv_bfloat162*)(g_enhi + off + 2) = __nv_bfloat162(hb[2], hb[3]);
        *(__nv_bfloat162*)(g_enlo + off)     = __nv_bfloat162(lb[0], lb[1]);
        *(__nv_bfloat162*)(g_enlo + off + 2) = __nv_bfloat162(lb[2], lb[3]);
    }
}

// ===================== prep: Mt[n][k] = [Mhi^T | Mlo^T | Mhi^T] =====================
__global__ void prep_bt_all(const float* __restrict__ U, const float* __restrict__ V,
                            const float* __restrict__ W) {
    int n = blockIdx.x & 255, which = blockIdx.x >> 8, k = threadIdx.x;
    const float* M = (which == 0) ? U : (which == 1) ? V : W;
    __nv_bfloat16* out = (which == 0) ? g_Ut : (which == 1) ? g_Vt : g_Wt;
    float v = M[(size_t)k*ND + n];
    __nv_bfloat16 hi = __float2bfloat16(v);
    __nv_bfloat16 lo = __float2bfloat16(v - __bfloat162float(hi));
    out[(size_t)n*KBIG + k]       = hi;
    out[(size_t)n*KBIG + 256 + k] = lo;
    out[(size_t)n*KBIG + 512 + k] = hi;
}

// ===================== split fp32 -> bf16 hi/lo (keys only) =====================
__global__ void split_kernel(const float* __restrict__ keys) {
    int i = blockIdx.x * blockDim.x + threadIdx.x;
    float v = keys[i];
    __nv_bfloat16 h = __float2bfloat16(v);
    g_kyhi[i] = h;
    g_kylo[i] = __float2bfloat16(v - __bfloat162float(h));
}

// ===================== HMMA prelude GEMM: kV = keys@V and eW = enc@W ================
__device__ __forceinline__ void ldsm_x2g(uint32_t* r, uint32_t addr) {
    asm volatile("ldmatrix.sync.aligned.m8n8.x2.shared.b16 {%0,%1}, [%2];"
        : "=r"(r[0]), "=r"(r[1]) : "r"(addr));
}

__global__ void __launch_bounds__(512, 1)
hmma_gemm0() {
    extern __shared__ char smem[];
    const uint32_t sb = smem_u32(smem);
    const int tid  = threadIdx.x;
    const int lane = tid & 31;
    const int wid  = tid >> 5;
    const int warp_m = wid >> 2, warp_n = wid & 3;
    const int bx = blockIdx.x;

    const __nv_bfloat16 *Ahi, *Alo, *Bt; float* C; int rowBase;
    if (bx < 128) { Ahi = g_kyhi; Alo = g_kylo; Bt = g_Vt; C = g_kV; rowBase = bx*128; }
    else          { Ahi = g_enhi; Alo = g_enlo; Bt = g_Wt; C = g_eW; rowBase = (bx-128)*128; }
    const __nv_bfloat16* hi = Ahi + (size_t)rowBase*ND;
    const __nv_bfloat16* lo = Alo + (size_t)rowBase*ND;

    const int selA = lane >> 3;
    const uint32_t aoff = (uint32_t)(((selA & 1)*8 + (lane & 7))*144 + (selA >> 1)*16);
    const int l16 = lane & 15;
    const uint32_t boff = (uint32_t)((l16 & 7)*144 + (l16 >> 3)*16);

    auto load_chunk = [&](int c, int slot) {
        const __nv_bfloat16* asrc = ((c < 8) ? hi : lo) + (c & 3)*64;
        const __nv_bfloat16* bsrc = Bt + c*64;
        uint32_t adst = sb + (uint32_t)slot*G_STAGE;
        uint32_t bdst = adst + G_A_TILE;
        #pragma unroll
        for (int i = 0; i < 2; i++) {
            int idx = tid + i*512, row = idx >> 3, seg = idx & 7;
            cpa16(adst + row*144 + seg*16, asrc + (size_t)row*ND + seg*8);
        }
        #pragma unroll
        for (int i = 0; i < 4; i++) {
            int idx = tid + i*512, n = idx >> 3, seg = idx & 7;
            cpa16(bdst + n*144 + seg*16, bsrc + (size_t)n*KBIG + seg*8);
        }
    };

    float acc[2][8][4];
    #pragma unroll
    for (int mt = 0; mt < 2; mt++)
        #pragma unroll
        for (int nt = 0; nt < 8; nt++)
            #pragma unroll
            for (int q = 0; q < 4; q++) acc[mt][nt][q] = 0.f;

    load_chunk(0, 0); CP_COMMIT();
    load_chunk(1, 1); CP_COMMIT();
    #pragma unroll
    for (int c = 0; c < 12; ++c) {
        if (c < 11) CP_WAIT1(); else CP_WAIT0();
        __syncthreads();
        if (c < 10) { load_chunk(c + 2, (c + 2) % 3); CP_COMMIT(); }
        const uint32_t base = sb + (uint32_t)(c % 3)*G_STAGE;
        const uint32_t abase = base + (warp_m*32)*144 + aoff;
        const uint32_t bbase = base + G_A_TILE + (warp_n*64)*144 + boff;
        #pragma unroll
        for (int k4 = 0; k4 < 4; ++k4) {
            const uint32_t kb = k4 * 32;
            uint32_t a0[4], a1[4];
            ldsm_x4(a0, abase + kb);
            ldsm_x4(a1, abase + 16*144 + kb);
            #pragma unroll
            for (int nt = 0; nt < 8; ++nt) {
                uint32_t bfrag[2];
                ldsm_x2g(bfrag, bbase + nt*8*144 + kb);
                mma_bf16(acc[0][nt], a0, bfrag);
                mma_bf16(acc[1][nt], a1, bfrag);
            }
        }
        __syncthreads();
    }

    #pragma unroll
    for (int mt = 0; mt < 2; mt++) {
        int rA = warp_m*32 + mt*16 + (lane >> 2);
        int rB = rA + 8;
        size_t gOA = (size_t)(rowBase + rA)*ND;
        size_t gOB = (size_t)(rowBase + rB)*ND;
        #pragma unroll
        for (int nt = 0; nt < 8; nt++) {
            int col = warp_n*64 + nt*8 + 2*(lane & 3);
            *(float2*)(C + gOA + col) = make_float2(acc[mt][nt][0], acc[mt][nt][1]);
            *(float2*)(C + gOB + col) = make_float2(acc[mt][nt][2], acc[mt][nt][3]);
        }
    }
}

// ===================== persistent fused recurrence: h state in SMEM, continuous ring ==
__global__ void __launch_bounds__(512, 1)
steps_kernel(const float* __restrict__ keys, float* __restrict__ h) {
    extern __shared__ char smem[];
    const uint32_t sb = smem_u32(smem);
    const int tid    = threadIdx.x;
    const int lane   = tid & 31;
    const int wid    = tid >> 5;
    const int warp_m = wid >> 2;          // 0..3 -> 32 rows
    const int warp_n = wid & 3;           // 0..3 -> 64 cols
    const int rowBase = blockIdx.x * 128;
    const int CTOT = (NS - 1) * 16;       // 496 chunks, continuous stream

    float* gs   = (float*)(smem + SM_GATE);
    float* rs   = (float*)(smem + SM_RSQ);
    float* dV   = (float*)(smem + SM_DV);
    float* dH   = (float*)(smem + SM_DH);
    float* gn   = (float*)(smem + SM_GN);
    int*   acts = (int*)  (smem + SM_ACTS);

    // B stream chunk loader: global chunk c -> q = c & 15, slot = c & 3
    auto load_chunk = [&](int c) {
        int q = c & 15;
        int kk = (q & 7) * 32;
        const __nv_bfloat16* bsrc = g_Ut + ((q < 8) ? kk : (256 + kk));
        uint32_t base = sb + SM_RING + (uint32_t)(c & 3)*STG;
        #pragma unroll
        for (int i = 0; i < 2; i++) {          // B: 256 rows x 4 segs of 16B
            int idx = tid + i*512, row = idx >> 2, seg = idx & 3;
            cpa16(base + row*80 + seg*16, bsrc + (size_t)row*KBIG + seg*8);
        }
    };

    // prime the ring (depth 3) BEFORE phase 0 so prefetch overlaps dek compute
    int cload = 0;
    #pragma unroll
    for (int i = 0; i < 3; i++) { load_chunk(cload); CP_COMMIT(); cload++; }

    // ---------- phase 0: g_dek[row][s] = dot(enc_s, keys_row) once ----------
    {
        int r = tid >> 2, part = tid & 3;
        int grow = rowBase + r, b = grow >> 6;
        float4 ky[16];
        const float4* kp = (const float4*)(keys + (size_t)grow*ND + part*64);
        #pragma unroll
        for (int i = 0; i < 16; i++) ky[i] = kp[i];
        for (int s = 0; s < NS; s++) {
            const float4* ep = (const float4*)(g_enc + ((size_t)b*NS + s)*ND + part*64);
            float d = 0.f;
            #pragma unroll
            for (int i = 0; i < 16; i++) {
                float4 e = ep[i];
                d += ky[i].x*e.x + ky[i].y*e.y + ky[i].z*e.z + ky[i].w*e.w;
            }
            d += __shfl_xor_sync(0xffffffffu, d, 1);
            d += __shfl_xor_sync(0xffffffffu, d, 2);
            if (part == 0) g_dek[(size_t)grow*NS + s] = d;
        }
        if (tid < 128) gn[tid] = 0.f;
    }

    // ---- per-lane constants ----
    const int lane7 = lane & 7;
    const int sel2  = lane >> 4;                         // k16-half select
    const uint32_t arow = (uint32_t)(warp_m*32 + ((lane >> 3) & 1)*8 + lane7) * 512;
    const uint32_t boff4 = (uint32_t)(((lane >> 4)*8 + lane7)*80 + ((lane >> 3) & 1)*16);
    const int r7 = (lane >> 2) & 7;
    const uint32_t ebyte = (uint32_t)((lane & 3)*4);

    float acc[2][8][4];

    auto compute = [&](int c) {
        int q = c & 15;
        uint32_t bB = sb + SM_RING + (uint32_t)(c & 3)*STG + (warp_n*64)*80 + boff4;
        const int kseg0 = (q & 7)*4 + sel2;
        #pragma unroll
        for (int k2 = 0; k2 < 2; ++k2) {
            const uint32_t kb = (uint32_t)k2*32;
            uint32_t bq[16];
            #pragma unroll
            for (int np = 0; np < 4; np++) ldsm_x4(&bq[np*4], bB + np*1280 + kb);
            const uint32_t seg = (uint32_t)((kseg0 + k2*2) ^ lane7) * 16;
            uint32_t aHa = sb + SM_AHI + arow + seg;
            uint32_t ah[8];
            ldsm_x4(ah,     aHa);
            ldsm_x4(ah + 4, aHa + 8192);
            #pragma unroll
            for (int np = 0; np < 4; np++) {
                mma_bf16(acc[0][2*np],   ah,     &bq[np*4]);
                mma_bf16(acc[0][2*np+1], ah,     &bq[np*4+2]);
                mma_bf16(acc[1][2*np],   ah + 4, &bq[np*4]);
                mma_bf16(acc[1][2*np+1], ah + 4, &bq[np*4+2]);
            }
            if (q < 8) {
                uint32_t aLa = sb + SM_ALO + arow + seg;
                uint32_t al[8];
                ldsm_x4(al,     aLa);
                ldsm_x4(al + 4, aLa + 8192);
                #pragma unroll
                for (int np = 0; np < 4; np++) {
                    mma_bf16(acc[0][2*np],   al,     &bq[np*4]);
                    mma_bf16(acc[0][2*np+1], al,     &bq[np*4+2]);
                    mma_bf16(acc[1][2*np],   al + 4, &bq[np*4]);
                    mma_bf16(acc[1][2*np+1], al + 4, &bq[np*4+2]);
                }
            }
        }
    };

    for (int s = 0; s < NS; ++s) {
        const bool first = (s == 0);
        const bool last  = (s == NS - 1);
        __syncthreads();                  // prev pass2 smem writes / phase0 done
        if (tid < 128) {
            int grow = rowBase + tid;
            int b = grow >> 6;
            gs[tid]   = 1.f / (1.f + expf(-(gn[tid] + g_dek[(size_t)grow*NS + s])));
            acts[tid] = g_act[b*NS + s];
            rs[tid] = 0.f; dV[tid] = 0.f; dH[tid] = 0.f;
        }

        #pragma unroll
        for (int mt = 0; mt < 2; mt++)
            #pragma unroll
            for (int nt = 0; nt < 8; nt++)
                #pragma unroll
                for (int q = 0; q < 4; q++) acc[mt][nt][q] = 0.f;

        if (!first) {
            const int c0 = (s - 1) * 16;
            for (int q = 0; q < 16; ++q) {
                const int c = c0 + q;
                const int rem = CTOT - 1 - c;
                if (rem >= 2) CP_WAIT2(); else if (rem == 1) CP_WAIT1(); else CP_WAIT0();
                __syncthreads();
                if (cload < CTOT) { load_chunk(cload); CP_COMMIT(); cload++; }
                compute(c);
            }
        } else {
            __syncthreads();
        }

        // ---------- epilogue pass 1 (h state read from persistent smem) ----------
        const int sn = (s + 1 < NS) ? s + 1 : NS - 1;
        #pragma unroll
        for (int mt = 0; mt < 2; mt++) {
            int rA = warp_m*32 + mt*16 + (lane >> 2);
            int rB = rA + 8;
            int gA = rowBase + rA, gB = rowBase + rB;
            int bA = gA >> 6;
            const float* kvA = g_kV + (size_t)gA*ND;
            const float* kvB = g_kV + (size_t)gB*ND;
            const float* ewR = g_eW  + ((size_t)bA*NS + s )*ND;
            const float* enN = g_enc + ((size_t)bA*NS + sn)*ND;
            float gateA = gs[rA], gateB = gs[rB];
            float sA = 0.f, sB = 0.f;
            float dVA = 0.f, dVB = 0.f, dHA = 0.f, dHB = 0.f;
            #pragma unroll
            for (int nt = 0; nt < 8; nt++) {
                int col = warp_n*64 + nt*8 + 2*(lane & 3);
                const uint32_t seg = (uint32_t)((warp_n*8 + nt) ^ r7) * 16;
                float2 en = *(const float2*)(enN + col);
                float2 ew = *(const float2*)(ewR + col);
                float2 kv, ho;
                kv = *(const float2*)(kvA + col);
                if (first) ho = make_float2(0.f, 0.f);
                else {
                    uint32_t offA = (uint32_t)rA*512 + seg + ebyte;
                    __nv_bfloat162 hb = *(__nv_bfloat162*)(smem + SM_AHI + offA);
                    __nv_bfloat162 lb = *(__nv_bfloat162*)(smem + SM_ALO + offA);
                    ho = make_float2(__bfloat162float(hb.x) + __bfloat162float(lb.x),
                                     __bfloat162float(hb.y) + __bfloat162float(lb.y));
                }
                float v0 = fmaxf(acc[mt][nt][0] + kv.x + ew.x, 0.f);
                float v1 = fmaxf(acc[mt][nt][1] + kv.y + ew.y, 0.f);
                float h0 = ho.x + gateA*v0, h1 = ho.y + gateA*v1;
                acc[mt][nt][0] = h0; acc[mt][nt][1] = h1;
                sA  += h0*h0 + h1*h1;
                dVA += en.x*h0 + en.y*h1;
                dHA += en.x*ho.x + en.y*ho.y;
                kv = *(const float2*)(kvB + col);
                if (first) ho = make_float2(0.f, 0.f);
                else {
                    uint32_t offB = (uint32_t)rB*512 + seg + ebyte;
                    __nv_bfloat162 hb = *(__nv_bfloat162*)(smem + SM_AHI + offB);
                    __nv_bfloat162 lb = *(__nv_bfloat162*)(smem + SM_ALO + offB);
                    ho = make_float2(__bfloat162float(hb.x) + __bfloat162float(lb.x),
                                     __bfloat162float(hb.y) + __bfloat162float(lb.y));
                }
                float w0 = fmaxf(acc[mt][nt][2] + kv.x + ew.x, 0.f);
                float w1 = fmaxf(acc[mt][nt][3] + kv.y + ew.y, 0.f);
                float h2 = ho.x + gateB*w0, h3 = ho.y + gateB*w1;
                acc[mt][nt][2] = h2; acc[mt][nt][3] = h3;
                sB  += h2*h2 + h3*h3;
                dVB += en.x*h2 + en.y*h3;
                dHB += en.x*ho.x + en.y*ho.y;
            }
            #pragma unroll
            for (int o = 1; o <= 2; o <<= 1) {
                sA  += __shfl_xor_sync(0xffffffffu, sA,  o);
                sB  += __shfl_xor_sync(0xffffffffu, sB,  o);
                dVA += __shfl_xor_sync(0xffffffffu, dVA, o);
                dVB += __shfl_xor_sync(0xffffffffu, dVB, o);
                dHA += __shfl_xor_sync(0xffffffffu, dHA, o);
                dHB += __shfl_xor_sync(0xffffffffu, dHB, o);
            }
            if ((lane & 3) == 0) {
                atomicAdd(&rs[rA], sA);  atomicAdd(&rs[rB], sB);
                atomicAdd(&dV[rA], dVA); atomicAdd(&dV[rB], dVB);
                atomicAdd(&dH[rA], dHA); atomicAdd(&dH[rB], dHB);
            }
        }
        __syncthreads();
        if (tid < 128) {
            float r = rsqrtf(fmaxf(rs[tid], 1e-12f));
            rs[tid] = r;
            gn[tid] = acts[tid] ? dV[tid]*r : dH[tid];
        }
        __syncthreads();

        // ---------- epilogue pass 2: normalize + write smem hi/lo (+h gmem at last) --
        #pragma unroll
        for (int mt = 0; mt < 2; mt++) {
            int rA = warp_m*32 + mt*16 + (lane >> 2);
            int rB = rA + 8;
            float rn2[2] = { rs[rA], rs[rB] };
            int   ac2[2] = { acts[rA], acts[rB] };
            int   rr2[2] = { rA, rB };
            #pragma unroll
            for (int half = 0; half < 2; half++) {
                float rn = rn2[half]; int aa = ac2[half]; int row = rr2[half];
                size_t gO = (size_t)(rowBase + row)*ND;
                #pragma unroll
                for (int nt = 0; nt < 8; nt++) {
                    int col = warp_n*64 + nt*8 + 2*(lane & 3);
                    uint32_t off = (uint32_t)row*512 + (uint32_t)((warp_n*8 + nt) ^ r7)*16 + ebyte;
                    float a0 = acc[mt][nt][half*2], a1 = acc[mt][nt][half*2+1];
                    if (aa || first) {
                        float v0 = aa ? a0*rn : 0.f;
                        float v1 = aa ? a1*rn : 0.f;
                        __nv_bfloat16 h0 = __float2bfloat16(v0), h1 = __float2bfloat16(v1);
                        *(__nv_bfloat162*)(smem + SM_AHI + off) = __nv_bfloat162(h0, h1);
                        *(__nv_bfloat162*)(smem + SM_ALO + off) = __nv_bfloat162(
                            __float2bfloat16(v0 - __bfloat162float(h0)),
                            __float2bfloat16(v1 - __bfloat162float(h1)));
                        if (last) *(float2*)(h + gO + col) = make_float2(v0, v1);
                    } else if (last) {
                        __nv_bfloat162 hb = *(__nv_bfloat162*)(smem + SM_AHI + off);
                        __nv_bfloat162 lb = *(__nv_bfloat162*)(smem + SM_ALO + off);
                        *(float2*)(h + gO + col) = make_float2(
                            __bfloat162float(hb.x) + __bfloat162float(lb.x),
                            __bfloat162float(hb.y) + __bfloat162float(lb.y));
                    }
                }
            }
        }
    }
}

// ===================== launch =====================
extern "C" void kernel_launch(void* const* d_in, const int* in_sizes, int n_in,
                              void* d_out, int out_size) {
    const int*   tok  = (const int*)  d_in[0];
    const float* mask = (const float*)d_in[1];
    const float* keys = (const float*)d_in[2];
    const float* emb  = (const float*)d_in[3];
    const float* U    = (const float*)d_in[4];
    const float* V    = (const float*)d_in[5];
    const float* W    = (const float*)d_in[6];
    float* h = (float*)d_out;

    cudaFuncSetAttribute(steps_kernel, cudaFuncAttributeMaxDynamicSharedMemorySize, SMEM_STEPS);
    cudaFuncSetAttribute(hmma_gemm0,   cudaFuncAttributeMaxDynamicSharedMemorySize, SMEM_G0);

    encode_kernel<<<NB*NS, 256>>>(tok, mask, emb);
    prep_bt_all<<<3*ND, ND>>>(U, V, W);
    split_kernel<<<(NB*NE*ND)/256, 256>>>(keys);
    hmma_gemm0<<<192, 512, SMEM_G0>>>();
    steps_kernel<<<128, 512, SMEM_STEPS>>>(keys, h);
}

// round 11
// speedup vs baseline: 1.3987x; 1.0124x over previous
#include <cuda_runtime.h>
#include <cuda_bf16.h>
#include <cstdint>
#include <math.h>

#define NB 256
#define NS 32
#define NL 32
#define ND 256
#define NE 64
#define KBIG 768          // Bt columns: [Hi | Lo | Hi-dup(unused)]

// ===================== scratch (device globals; no runtime alloc) =====================
__device__ float g_enc[NB*NS*ND];            // enc[b,s,d]
__device__ float g_eW [NB*NS*ND];            // enc @ W
__device__ float g_kV [NB*NE*ND];            // keys @ V
__device__ int   g_act[NB*NS];
__device__ float g_dek[NB*NE*NS];            // dot(enc_s, keys_row), [row][s]
__device__ __nv_bfloat16 g_Ut[ND*KBIG];      // U^T  [Hi|Lo|Hi]
__device__ __nv_bfloat16 g_Vt[ND*KBIG];      // V^T  [Hi|Lo|Hi]
__device__ __nv_bfloat16 g_Wt[ND*KBIG];      // W^T  [Hi|Lo|Hi]
__device__ __nv_bfloat16 g_kyhi[NB*NE*ND];   // keys split
__device__ __nv_bfloat16 g_kylo[NB*NE*ND];
__device__ __nv_bfloat16 g_enhi[NB*NS*ND];   // enc split
__device__ __nv_bfloat16 g_enlo[NB*NS*ND];

// ===================== PTX wrappers =====================
__device__ __forceinline__ uint32_t smem_u32(const void* p) {
    uint32_t a;
    asm("{ .reg .u64 t; cvta.to.shared.u64 t, %1; cvt.u32.u64 %0, t; }" : "=r"(a) : "l"(p));
    return a;
}
__device__ __forceinline__ void cpa16(uint32_t dst, const void* src) {
    asm volatile("cp.async.cg.shared.global [%0], [%1], 16;" :: "r"(dst), "l"(src));
}
#define CP_COMMIT() asm volatile("cp.async.commit_group;" ::: "memory")
#define CP_WAIT2()  asm volatile("cp.async.wait_group 2;"  ::: "memory")
#define CP_WAIT1()  asm volatile("cp.async.wait_group 1;"  ::: "memory")
#define CP_WAIT0()  asm volatile("cp.async.wait_group 0;"  ::: "memory")

__device__ __forceinline__ void ldsm_x4(uint32_t* r, uint32_t addr) {
    asm volatile("ldmatrix.sync.aligned.m8n8.x4.shared.b16 {%0,%1,%2,%3}, [%4];"
        : "=r"(r[0]), "=r"(r[1]), "=r"(r[2]), "=r"(r[3]) : "r"(addr));
}
__device__ __forceinline__ void mma_bf16(float* d, const uint32_t* a, const uint32_t* b) {
    asm volatile("mma.sync.aligned.m16n8k16.row.col.f32.bf16.bf16.f32 "
        "{%0,%1,%2,%3}, {%4,%5,%6,%7}, {%8,%9}, {%0,%1,%2,%3};"
        : "+f"(d[0]), "+f"(d[1]), "+f"(d[2]), "+f"(d[3])
        : "r"(a[0]), "r"(a[1]), "r"(a[2]), "r"(a[3]), "r"(b[0]), "r"(b[1]));
}

// ===================== steps smem layout ==============
#define SM_GATE 0
#define SM_RSQ  512
#define SM_GN   1024
#define SM_ACTS 1536
#define SM_RS4  2048                        // [4][128] floats
#define SM_DV4  4096
#define SM_DH4  6144
#define SM_AHI  8192                        // 128 rows * 512B (xor-swizzled)
#define SM_ALO  (8192 + 65536)
#define SM_RING (8192 + 131072)             // 139264
#define STG     20480
#define SMEM_STEPS (SM_RING + 4*STG)        // 221184

// ===================== encode (vectorized, + bf16 split fold-in) =====================
__global__ __launch_bounds__(256)
void encode_kernel(const int* __restrict__ tok, const float* __restrict__ mask,
                   const float* __restrict__ emb) {
    __shared__ float4 red[4][64];
    const int bs = blockIdx.x, tid = threadIdx.x;
    const int lg = tid >> 6, d4 = tid & 63;
    const int*   t = tok  + (size_t)bs*NL;
    const float* m = mask + (size_t)bs*NL;

    if (tid < 32) {
        float mv = m[tid];
        #pragma unroll
        for (int o = 16; o > 0; o >>= 1) mv += __shfl_xor_sync(0xffffffffu, mv, o);
        if (tid == 0) g_act[bs] = (mv > 0.f) ? 1 : 0;
    }

    float4 acc = make_float4(0.f, 0.f, 0.f, 0.f);
    #pragma unroll
    for (int i = 0; i < 8; i++) {
        int l = lg*8 + i;
        float mv = __ldg(m + l);
        int   tv = __ldg(t + l);
        float4 e = __ldg((const float4*)(emb + (size_t)tv*ND) + d4);
        acc.x += mv*e.x; acc.y += mv*e.y; acc.z += mv*e.z; acc.w += mv*e.w;
    }
    red[lg][d4] = acc;
    __syncthreads();
    if (lg == 0) {
        float4 a = red[0][d4], b = red[1][d4], c = red[2][d4], d = red[3][d4];
        float4 v = make_float4(a.x+b.x+c.x+d.x, a.y+b.y+c.y+d.y,
                               a.z+b.z+c.z+d.z, a.w+b.w+c.w+d.w);
        size_t off = (size_t)bs*ND + d4*4;
        *(float4*)(g_enc + off) = v;
        float vv[4] = {v.x, v.y, v.z, v.w};
        __nv_bfloat16 hb[4], lb[4];
        #pragma unroll
        for (int i = 0; i < 4; i++) {
            hb[i] = __float2bfloat16(vv[i]);
            lb[i] = __float2bfloat16(vv[i] - __bfloat162float(hb[i]));
        }
        *(__nv_bfloat162*)(g_enhi + off)     = __nv_bfloat162(hb[0], hb[1]);
        *(__nv_bfloat162*)(g_enhi + off + 2) = __nv_bfloat162(hb[2], hb[3]);
        *(__nv_bfloat162*)(g_enlo + off)     = __nv_bfloat162(lb[0], lb[1]);
        *(__nv_bfloat162*)(g_enlo + off + 2) = __nv_bfloat162(lb[2], lb[3]);
    }
}

// ===================== prep: Mt[n][k] = [Mhi^T | Mlo^T | Mhi^T] =====================
__global__ void prep_bt_all(const float* __restrict__ U, const float* __restrict__ V,
                            const float* __restrict__ W) {
    int n = blockIdx.x & 255, which = blockIdx.x >> 8, k = threadIdx.x;
    const float* M = (which == 0) ? U : (which == 1) ? V : W;
    __nv_bfloat16* out = (which == 0) ? g_Ut : (which == 1) ? g_Vt : g_Wt;
    float v = M[(size_t)k*ND + n];
    __nv_bfloat16 hi = __float2bfloat16(v);
    __nv_bfloat16 lo = __float2bfloat16(v - __bfloat162float(hi));
    out[(size_t)n*KBIG + k]       = hi;
    out[(size_t)n*KBIG + 256 + k] = lo;
    out[(size_t)n*KBIG + 512 + k] = hi;
}

// ===================== split fp32 -> bf16 hi/lo (keys only) =====================
__global__ void split_kernel(const float* __restrict__ keys) {
    int i = blockIdx.x * blockDim.x + threadIdx.x;
    float v = keys[i];
    __nv_bfloat16 h = __float2bfloat16(v);
    g_kyhi[i] = h;
    g_kylo[i] = __float2bfloat16(v - __bfloat162float(h));
}

// ===================== persistent fused kernel: kV + eW + 32-step recurrence =========
__global__ void __launch_bounds__(512, 1)
steps_kernel(const float* __restrict__ keys, float* __restrict__ h) {
    extern __shared__ char smem[];
    const uint32_t sb = smem_u32(smem);
    const int tid    = threadIdx.x;
    const int lane   = tid & 31;
    const int wid    = tid >> 5;
    const int warp_m = wid >> 2;          // 0..3 -> 32 rows
    const int warp_n = wid & 3;           // 0..3 -> 64 cols
    const int rowBase = blockIdx.x * 128;
    const int bA0 = rowBase >> 6;         // first of 2 b's this CTA owns
    const int CTOT = 32 + (NS - 1) * 16;  // 16 Vt + 16 Wt + 496 Ut = 528

    float* gs   = (float*)(smem + SM_GATE);
    float* rs   = (float*)(smem + SM_RSQ);
    float* gn   = (float*)(smem + SM_GN);
    int*   acts = (int*)  (smem + SM_ACTS);

    // ---- B stream: chunk c -> q = c&15, slot = c&3; source Vt / Wt / Ut by phase ----
    auto load_chunk = [&](int c) {
        int q = c & 15;
        const __nv_bfloat16* mat = (c < 16) ? g_Vt : (c < 32) ? g_Wt : g_Ut;
        int kk = (q & 7) * 32;
        const __nv_bfloat16* bsrc = mat + ((q < 8) ? kk : (256 + kk));
        uint32_t base = sb + SM_RING + (uint32_t)(c & 3)*STG;
        #pragma unroll
        for (int i = 0; i < 2; i++) {
            int idx = tid + i*512, row = idx >> 2, seg = idx & 3;
            cpa16(base + row*80 + seg*16, bsrc + (size_t)row*KBIG + seg*8);
        }
    };

    // ---- A smem loader (plain LDG/STS), nrows = 128 or 64 ----
    auto load_A = [&](const __nv_bfloat16* srcHi, const __nv_bfloat16* srcLo, int niter) {
        for (int i = 0; i < niter; i++) {
            int idx = tid + i*512;
            int row = idx >> 5, seg = idx & 31;
            uint32_t dst = (uint32_t)row*512 + (uint32_t)((seg ^ (row & 7))*16);
            *(uint4*)(smem + SM_AHI + dst) = *(const uint4*)(srcHi + (size_t)row*ND + seg*8);
            *(uint4*)(smem + SM_ALO + dst) = *(const uint4*)(srcLo + (size_t)row*ND + seg*8);
        }
    };

    int cload = 0;
    #pragma unroll
    for (int i = 0; i < 3; i++) { load_chunk(cload); CP_COMMIT(); cload++; }

    // ---------- phase 0: g_dek[row][s] = dot(enc_s, keys_row) (overlaps prefetch) ----
    {
        int r = tid >> 2, part = tid & 3;
        int grow = rowBase + r, b = grow >> 6;
        float4 ky[16];
        const float4* kp = (const float4*)(keys + (size_t)grow*ND + part*64);
        #pragma unroll
        for (int i = 0; i < 16; i++) ky[i] = kp[i];
        for (int s = 0; s < NS; s++) {
            const float4* ep = (const float4*)(g_enc + ((size_t)b*NS + s)*ND + part*64);
            float d = 0.f;
            #pragma unroll
            for (int i = 0; i < 16; i++) {
                float4 e = ep[i];
                d += ky[i].x*e.x + ky[i].y*e.y + ky[i].z*e.z + ky[i].w*e.w;
            }
            d += __shfl_xor_sync(0xffffffffu, d, 1);
            d += __shfl_xor_sync(0xffffffffu, d, 2);
            if (part == 0) g_dek[(size_t)grow*NS + s] = d;
        }
        if (tid < 128) gn[tid] = 0.f;
    }

    // ---- per-lane constants ----
    const int lane7 = lane & 7;
    const int sel2  = lane >> 4;
    const uint32_t arow = (uint32_t)(warp_m*32 + ((lane >> 3) & 1)*8 + lane7) * 512;
    const uint32_t boff4 = (uint32_t)(((lane >> 4)*8 + lane7)*80 + ((lane >> 3) & 1)*16);
    const int r7 = (lane >> 2) & 7;
    const uint32_t ebyte = (uint32_t)((lane & 3)*4);

    float acc[2][8][4];
    auto zero_acc = [&]() {
        #pragma unroll
        for (int mt = 0; mt < 2; mt++)
            #pragma unroll
            for (int nt = 0; nt < 8; nt++)
                #pragma unroll
                for (int q = 0; q < 4; q++) acc[mt][nt][q] = 0.f;
    };

    auto compute = [&](int c) {
        int q = c & 15;
        uint32_t bB = sb + SM_RING + (uint32_t)(c & 3)*STG + (warp_n*64)*80 + boff4;
        const int kseg0 = (q & 7)*4 + sel2;
        #pragma unroll
        for (int k2 = 0; k2 < 2; ++k2) {
            const uint32_t kb = (uint32_t)k2*32;
            uint32_t bq[16];
            #pragma unroll
            for (int np = 0; np < 4; np++) ldsm_x4(&bq[np*4], bB + np*1280 + kb);
            const uint32_t seg = (uint32_t)((kseg0 + k2*2) ^ lane7) * 16;
            uint32_t aHa = sb + SM_AHI + arow + seg;
            uint32_t ah[8];
            ldsm_x4(ah,     aHa);
            ldsm_x4(ah + 4, aHa + 8192);
            #pragma unroll
            for (int np = 0; np < 4; np++) {
                mma_bf16(acc[0][2*np],   ah,     &bq[np*4]);
                mma_bf16(acc[0][2*np+1], ah,     &bq[np*4+2]);
                mma_bf16(acc[1][2*np],   ah + 4, &bq[np*4]);
                mma_bf16(acc[1][2*np+1], ah + 4, &bq[np*4+2]);
            }
            if (q < 8) {
                uint32_t aLa = sb + SM_ALO + arow + seg;
                uint32_t al[8];
                ldsm_x4(al,     aLa);
                ldsm_x4(al + 4, aLa + 8192);
                #pragma unroll
                for (int np = 0; np < 4; np++) {
                    mma_bf16(acc[0][2*np],   al,     &bq[np*4]);
                    mma_bf16(acc[0][2*np+1], al,     &bq[np*4+2]);
                    mma_bf16(acc[1][2*np],   al + 4, &bq[np*4]);
                    mma_bf16(acc[1][2*np+1], al + 4, &bq[np*4+2]);
                }
            }
        }
    };

    auto run16 = [&](int c0) {
        for (int i = 0; i < 16; ++i) {
            const int c = c0 + i;
            const int pend = cload - 1 - c;
            if (pend >= 2) CP_WAIT2(); else if (pend == 1) CP_WAIT1(); else CP_WAIT0();
            __syncthreads();
            if (cload < CTOT) { load_chunk(cload); CP_COMMIT(); cload++; }
            compute(c);
        }
    };

    // ---------- phase 1: kV = keys @ V for this CTA's 128 rows ----------
    load_A(g_kyhi + (size_t)rowBase*ND, g_kylo + (size_t)rowBase*ND, 8);
    __syncthreads();
    zero_acc();
    run16(0);
    __syncthreads();
    #pragma unroll
    for (int mt = 0; mt < 2; mt++) {
        int rA = warp_m*32 + mt*16 + (lane >> 2);
        int rB = rA + 8;
        size_t gOA = (size_t)(rowBase + rA)*ND;
        size_t gOB = (size_t)(rowBase + rB)*ND;
        #pragma unroll
        for (int nt = 0; nt < 8; nt++) {
            int col = warp_n*64 + nt*8 + 2*(lane & 3);
            *(float2*)(g_kV + gOA + col) = make_float2(acc[mt][nt][0], acc[mt][nt][1]);
            *(float2*)(g_kV + gOB + col) = make_float2(acc[mt][nt][2], acc[mt][nt][3]);
        }
    }

    // ---------- phase 2: eW = enc @ W for this CTA's 64 enc rows ----------
    load_A(g_enhi + (size_t)(bA0*32)*ND, g_enlo + (size_t)(bA0*32)*ND, 4);
    __syncthreads();
    zero_acc();
    run16(16);
    __syncthreads();
    if (warp_m < 2) {
        #pragma unroll
        for (int mt = 0; mt < 2; mt++) {
            int rA = warp_m*32 + mt*16 + (lane >> 2);
            int rB = rA + 8;
            size_t gOA = (size_t)(bA0*32 + rA)*ND;
            size_t gOB = (size_t)(bA0*32 + rB)*ND;
            #pragma unroll
            for (int nt = 0; nt < 8; nt++) {
                int col = warp_n*64 + nt*8 + 2*(lane & 3);
                *(float2*)(g_eW + gOA + col) = make_float2(acc[mt][nt][0], acc[mt][nt][1]);
                *(float2*)(g_eW + gOB + col) = make_float2(acc[mt][nt][2], acc[mt][nt][3]);
            }
        }
    }

    // ---------- phase 3: the 32-step recurrence ----------
    for (int s = 0; s < NS; ++s) {
        const bool first = (s == 0);
        const bool last  = (s == NS - 1);
        __syncthreads();
        if (tid < 128) {
            int grow = rowBase + tid;
            int b = grow >> 6;
            gs[tid]   = 1.f / (1.f + expf(-(gn[tid] + g_dek[(size_t)grow*NS + s])));
            acts[tid] = g_act[b*NS + s];
        }

        zero_acc();

        if (!first) {
            run16(32 + (s - 1)*16);
        } else {
            __syncthreads();
        }

        // ---------- epilogue pass 1 (h state from persistent smem) ----------
        const int sn = (s + 1 < NS) ? s + 1 : NS - 1;
        #pragma unroll
        for (int mt = 0; mt < 2; mt++) {
            int rA = warp_m*32 + mt*16 + (lane >> 2);
            int rB = rA + 8;
            int gA = rowBase + rA, gB = rowBase + rB;
            int bA = gA >> 6;
            const float* kvA = g_kV + (size_t)gA*ND;
            const float* kvB = g_kV + (size_t)gB*ND;
            const float* ewR = g_eW  + ((size_t)bA*NS + s )*ND;
            const float* enN = g_enc + ((size_t)bA*NS + sn)*ND;
            float gateA = gs[rA], gateB = gs[rB];
            float sA = 0.f, sB = 0.f;
            float dVA = 0.f, dVB = 0.f, dHA = 0.f, dHB = 0.f;
            #pragma unroll
            for (int nt = 0; nt < 8; nt++) {
                int col = warp_n*64 + nt*8 + 2*(lane & 3);
                const uint32_t seg = (uint32_t)((warp_n*8 + nt) ^ r7) * 16;
                float2 en = *(const float2*)(enN + col);
                float2 ew = *(const float2*)(ewR + col);
                float2 kv, ho;
                kv = *(const float2*)(kvA + col);
                if (first) ho = make_float2(0.f, 0.f);
                else {
                    uint32_t offA = (uint32_t)rA*512 + seg + ebyte;
                    __nv_bfloat162 hb = *(__nv_bfloat162*)(smem + SM_AHI + offA);
                    __nv_bfloat162 lb = *(__nv_bfloat162*)(smem + SM_ALO + offA);
                    ho = make_float2(__bfloat162float(hb.x) + __bfloat162float(lb.x),
                                     __bfloat162float(hb.y) + __bfloat162float(lb.y));
                }
                float v0 = fmaxf(acc[mt][nt][0] + kv.x + ew.x, 0.f);
                float v1 = fmaxf(acc[mt][nt][1] + kv.y + ew.y, 0.f);
                float h0 = ho.x + gateA*v0, h1 = ho.y + gateA*v1;
                acc[mt][nt][0] = h0; acc[mt][nt][1] = h1;
                sA  += h0*h0 + h1*h1;
                dVA += en.x*h0 + en.y*h1;
                dHA += en.x*ho.x + en.y*ho.y;
                kv = *(const float2*)(kvB + col);
                if (first) ho = make_float2(0.f, 0.f);
                else {
                    uint32_t offB = (uint32_t)rB*512 + seg + ebyte;
                    __nv_bfloat162 hb = *(__nv_bfloat162*)(smem + SM_AHI + offB);
                    __nv_bfloat162 lb = *(__nv_bfloat162*)(smem + SM_ALO + offB);
                    ho = make_float2(__bfloat162float(hb.x) + __bfloat162float(lb.x),
                                     __bfloat162float(hb.y) + __bfloat162float(lb.y));
                }
                float w0 = fmaxf(acc[mt][nt][2] + kv.x + ew.x, 0.f);
                float w1 = fmaxf(acc[mt][nt][3] + kv.y + ew.y, 0.f);
                float h2 = ho.x + gateB*w0, h3 = ho.y + gateB*w1;
                acc[mt][nt][2] = h2; acc[mt][nt][3] = h3;
                sB  += h2*h2 + h3*h3;
                dVB += en.x*h2 + en.y*h3;
                dHB += en.x*ho.x + en.y*ho.y;
            }
            #pragma unroll
            for (int o = 1; o <= 2; o <<= 1) {
                sA  += __shfl_xor_sync(0xffffffffu, sA,  o);
                sB  += __shfl_xor_sync(0xffffffffu, sB,  o);
                dVA += __shfl_xor_sync(0xffffffffu, dVA, o);
                dVB += __shfl_xor_sync(0xffffffffu, dVB, o);
                dHA += __shfl_xor_sync(0xffffffffu, dHA, o);
                dHB += __shfl_xor_sync(0xffffffffu, dHB, o);
            }
            if ((lane & 3) == 0) {
                float* rs4 = (float*)(smem + SM_RS4) + warp_n*128;
                float* dv4 = (float*)(smem + SM_DV4) + warp_n*128;
                float* dh4 = (float*)(smem + SM_DH4) + warp_n*128;
                rs4[rA] = sA;  rs4[rB] = sB;
                dv4[rA] = dVA; dv4[rB] = dVB;
                dh4[rA] = dHA; dh4[rB] = dHB;
            }
        }
        __syncthreads();
        if (tid < 128) {
            const float* rs4 = (const float*)(smem + SM_RS4);
            const float* dv4 = (const float*)(smem + SM_DV4);
            const float* dh4 = (const float*)(smem + SM_DH4);
            float sq = rs4[tid] + rs4[128+tid] + rs4[256+tid] + rs4[384+tid];
            float dv = dv4[tid] + dv4[128+tid] + dv4[256+tid] + dv4[384+tid];
            float dh = dh4[tid] + dh4[128+tid] + dh4[256+tid] + dh4[384+tid];
            float r = rsqrtf(fmaxf(sq, 1e-12f));
            rs[tid] = r;
            gn[tid] = acts[tid] ? dv*r : dh;
        }
        __syncthreads();

        // ---------- epilogue pass 2: normalize + write smem hi/lo (+h gmem at last) --
        #pragma unroll
        for (int mt = 0; mt < 2; mt++) {
            int rA = warp_m*32 + mt*16 + (lane >> 2);
            int rB = rA + 8;
            float rn2[2] = { rs[rA], rs[rB] };
            int   ac2[2] = { acts[rA], acts[rB] };
            int   rr2[2] = { rA, rB };
            #pragma unroll
            for (int half = 0; half < 2; half++) {
                float rn = rn2[half]; int aa = ac2[half]; int row = rr2[half];
                size_t gO = (size_t)(rowBase + row)*ND;
                #pragma unroll
                for (int nt = 0; nt < 8; nt++) {
                    int col = warp_n*64 + nt*8 + 2*(lane & 3);
                    uint32_t off = (uint32_t)row*512 + (uint32_t)((warp_n*8 + nt) ^ r7)*16 + ebyte;
                    float a0 = acc[mt][nt][half*2], a1 = acc[mt][nt][half*2+1];
                    if (aa || first) {
                        float v0 = aa ? a0*rn : 0.f;
                        float v1 = aa ? a1*rn : 0.f;
                        __nv_bfloat16 h0 = __float2bfloat16(v0), h1 = __float2bfloat16(v1);
                        *(__nv_bfloat162*)(smem + SM_AHI + off) = __nv_bfloat162(h0, h1);
                        *(__nv_bfloat162*)(smem + SM_ALO + off) = __nv_bfloat162(
                            __float2bfloat16(v0 - __bfloat162float(h0)),
                            __float2bfloat16(v1 - __bfloat162float(h1)));
                        if (last) *(float2*)(h + gO + col) = make_float2(v0, v1);
                    } else if (last) {
                        __nv_bfloat162 hb = *(__nv_bfloat162*)(smem + SM_AHI + off);
                        __nv_bfloat162 lb = *(__nv_bfloat162*)(smem + SM_ALO + off);
                        *(float2*)(h + gO + col) = make_float2(
                            __bfloat162float(hb.x) + __bfloat162float(lb.x),
                            __bfloat162float(hb.y) + __bfloat162float(lb.y));
                    }
                }
            }
        }
    }
}

// ===================== launch =====================
extern "C" void kernel_launch(void* const* d_in, const int* in_sizes, int n_in,
                              void* d_out, int out_size) {
    const int*   tok  = (const int*)  d_in[0];
    const float* mask = (const float*)d_in[1];
    const float* keys = (const float*)d_in[2];
    const float* emb  = (const float*)d_in[3];
    const float* U    = (const float*)d_in[4];
    const float* V    = (const float*)d_in[5];
    const float* W    = (const float*)d_in[6];
    float* h = (float*)d_out;

    cudaFuncSetAttribute(steps_kernel, cudaFuncAttributeMaxDynamicSharedMemorySize, SMEM_STEPS);

    encode_kernel<<<NB*NS, 256>>>(tok, mask, emb);
    prep_bt_all<<<3*ND, ND>>>(U, V, W);
    split_kernel<<<(NB*NE*ND)/256, 256>>>(keys);
    steps_kernel<<<128, 512, SMEM_STEPS>>>(keys, h);
}

// round 12
// speedup vs baseline: 1.4238x; 1.0179x over previous
#include <cuda_runtime.h>
#include <cuda_bf16.h>
#include <cstdint>
#include <math.h>

#define NB 256
#define NS 32
#define NL 32
#define ND 256
#define NE 64
#define KBIG 768          // Bt columns: [Hi | Lo | Hi-dup(unused)]

// ===================== scratch (device globals; no runtime alloc) =====================
__device__ float g_enc[NB*NS*ND];            // enc[b,s,d]
__device__ float g_eW [NB*NS*ND];            // enc @ W
__device__ float g_kV [NB*NE*ND];            // keys @ V
__device__ int   g_act[NB*NS];
__device__ float g_dek[NB*NE*NS];            // dot(enc_s, keys_row), [row][s]
__device__ __nv_bfloat16 g_Ut[ND*KBIG];      // U^T  [Hi|Lo|Hi]
__device__ __nv_bfloat16 g_Vt[ND*KBIG];      // V^T  [Hi|Lo|Hi]
__device__ __nv_bfloat16 g_Wt[ND*KBIG];      // W^T  [Hi|Lo|Hi]
__device__ __nv_bfloat16 g_kyhi[NB*NE*ND];   // keys split
__device__ __nv_bfloat16 g_kylo[NB*NE*ND];
__device__ __nv_bfloat16 g_enhi[NB*NS*ND];   // enc split
__device__ __nv_bfloat16 g_enlo[NB*NS*ND];

// ===================== PTX wrappers =====================
__device__ __forceinline__ uint32_t smem_u32(const void* p) {
    uint32_t a;
    asm("{ .reg .u64 t; cvta.to.shared.u64 t, %1; cvt.u32.u64 %0, t; }" : "=r"(a) : "l"(p));
    return a;
}
__device__ __forceinline__ void cpa16(uint32_t dst, const void* src) {
    asm volatile("cp.async.cg.shared.global [%0], [%1], 16;" :: "r"(dst), "l"(src));
}
#define CP_COMMIT() asm volatile("cp.async.commit_group;" ::: "memory")
#define CP_WAIT2()  asm volatile("cp.async.wait_group 2;"  ::: "memory")
#define CP_WAIT1()  asm volatile("cp.async.wait_group 1;"  ::: "memory")
#define CP_WAIT0()  asm volatile("cp.async.wait_group 0;"  ::: "memory")

__device__ __forceinline__ void ldsm_x4(uint32_t* r, uint32_t addr) {
    asm volatile("ldmatrix.sync.aligned.m8n8.x4.shared.b16 {%0,%1,%2,%3}, [%4];"
        : "=r"(r[0]), "=r"(r[1]), "=r"(r[2]), "=r"(r[3]) : "r"(addr));
}
__device__ __forceinline__ void mma_bf16(float* d, const uint32_t* a, const uint32_t* b) {
    asm volatile("mma.sync.aligned.m16n8k16.row.col.f32.bf16.bf16.f32 "
        "{%0,%1,%2,%3}, {%4,%5,%6,%7}, {%8,%9}, {%0,%1,%2,%3};"
        : "+f"(d[0]), "+f"(d[1]), "+f"(d[2]), "+f"(d[3])
        : "r"(a[0]), "r"(a[1]), "r"(a[2]), "r"(a[3]), "r"(b[0]), "r"(b[1]));
}

// ===================== steps smem layout ==============
#define SM_GATE 0
#define SM_RSQ  512
#define SM_GN   1024
#define SM_ACTS 1536
#define SM_RS4  2048                        // [4][128] floats
#define SM_DV4  4096
#define SM_DH4  6144
#define SM_AHI  8192                        // 128 rows * 512B (xor-swizzled)
#define SM_ALO  (8192 + 65536)
#define SM_RING (8192 + 131072)             // 139264
#define STG     20480
#define SMEM_STEPS (SM_RING + 4*STG)        // 221184

// ===================== encode (vectorized, + bf16 split fold-in) =====================
__global__ __launch_bounds__(256)
void encode_kernel(const int* __restrict__ tok, const float* __restrict__ mask,
                   const float* __restrict__ emb) {
    __shared__ float4 red[4][64];
    const int bs = blockIdx.x, tid = threadIdx.x;
    const int lg = tid >> 6, d4 = tid & 63;
    const int*   t = tok  + (size_t)bs*NL;
    const float* m = mask + (size_t)bs*NL;

    if (tid < 32) {
        float mv = m[tid];
        #pragma unroll
        for (int o = 16; o > 0; o >>= 1) mv += __shfl_xor_sync(0xffffffffu, mv, o);
        if (tid == 0) g_act[bs] = (mv > 0.f) ? 1 : 0;
    }

    float4 acc = make_float4(0.f, 0.f, 0.f, 0.f);
    #pragma unroll
    for (int i = 0; i < 8; i++) {
        int l = lg*8 + i;
        float mv = __ldg(m + l);
        int   tv = __ldg(t + l);
        float4 e = __ldg((const float4*)(emb + (size_t)tv*ND) + d4);
        acc.x += mv*e.x; acc.y += mv*e.y; acc.z += mv*e.z; acc.w += mv*e.w;
    }
    red[lg][d4] = acc;
    __syncthreads();
    if (lg == 0) {
        float4 a = red[0][d4], b = red[1][d4], c = red[2][d4], d = red[3][d4];
        float4 v = make_float4(a.x+b.x+c.x+d.x, a.y+b.y+c.y+d.y,
                               a.z+b.z+c.z+d.z, a.w+b.w+c.w+d.w);
        size_t off = (size_t)bs*ND + d4*4;
        *(float4*)(g_enc + off) = v;
        float vv[4] = {v.x, v.y, v.z, v.w};
        __nv_bfloat16 hb[4], lb[4];
        #pragma unroll
        for (int i = 0; i < 4; i++) {
            hb[i] = __float2bfloat16(vv[i]);
            lb[i] = __float2bfloat16(vv[i] - __bfloat162float(hb[i]));
        }
        *(__nv_bfloat162*)(g_enhi + off)     = __nv_bfloat162(hb[0], hb[1]);
        *(__nv_bfloat162*)(g_enhi + off + 2) = __nv_bfloat162(hb[2], hb[3]);
        *(__nv_bfloat162*)(g_enlo + off)     = __nv_bfloat162(lb[0], lb[1]);
        *(__nv_bfloat162*)(g_enlo + off + 2) = __nv_bfloat162(lb[2], lb[3]);
    }
}

// ===================== prep: Mt[n][k] = [Mhi^T | Mlo^T | Mhi^T] =====================
__global__ void prep_bt_all(const float* __restrict__ U, const float* __restrict__ V,
                            const float* __restrict__ W) {
    int n = blockIdx.x & 255, which = blockIdx.x >> 8, k = threadIdx.x;
    const float* M = (which == 0) ? U : (which == 1) ? V : W;
    __nv_bfloat16* out = (which == 0) ? g_Ut : (which == 1) ? g_Vt : g_Wt;
    float v = M[(size_t)k*ND + n];
    __nv_bfloat16 hi = __float2bfloat16(v);
    __nv_bfloat16 lo = __float2bfloat16(v - __bfloat162float(hi));
    out[(size_t)n*KBIG + k]       = hi;
    out[(size_t)n*KBIG + 256 + k] = lo;
    out[(size_t)n*KBIG + 512 + k] = hi;
}

// ===================== split fp32 -> bf16 hi/lo (keys only) =====================
__global__ void split_kernel(const float* __restrict__ keys) {
    int i = blockIdx.x * blockDim.x + threadIdx.x;
    float v = keys[i];
    __nv_bfloat16 h = __float2bfloat16(v);
    g_kyhi[i] = h;
    g_kylo[i] = __float2bfloat16(v - __bfloat162float(h));
}

// ===================== persistent fused kernel: kV + eW + 32-step recurrence =========
__global__ void __launch_bounds__(512, 1)
steps_kernel(const float* __restrict__ keys, float* __restrict__ h) {
    extern __shared__ char smem[];
    const uint32_t sb = smem_u32(smem);
    const int tid    = threadIdx.x;
    const int lane   = tid & 31;
    const int wid    = tid >> 5;
    const int warp_m = wid >> 2;          // 0..3 -> 32 rows
    const int warp_n = wid & 3;           // 0..3 -> 64 cols
    const int rowBase = blockIdx.x * 128;
    const int bA0 = rowBase >> 6;         // first of 2 b's this CTA owns
    const int CTOT = 32 + (NS - 1) * 16;  // 16 Vt + 16 Wt + 496 Ut = 528

    float* gs   = (float*)(smem + SM_GATE);
    float* rs   = (float*)(smem + SM_RSQ);
    float* gn   = (float*)(smem + SM_GN);
    int*   acts = (int*)  (smem + SM_ACTS);

    // ---- B stream: chunk c; pair p = (c&15)>>1, kk = p*32; even=Hi, odd=Lo ----
    auto load_chunk = [&](int c) {
        int q = c & 15;
        int kk = (q >> 1) * 32;
        const __nv_bfloat16* mat = (c < 16) ? g_Vt : (c < 32) ? g_Wt : g_Ut;
        const __nv_bfloat16* bsrc = mat + ((q & 1) ? (256 + kk) : kk);
        uint32_t base = sb + SM_RING + (uint32_t)(c & 3)*STG;
        #pragma unroll
        for (int i = 0; i < 2; i++) {
            int idx = tid + i*512, row = idx >> 2, seg = idx & 3;
            cpa16(base + row*80 + seg*16, bsrc + (size_t)row*KBIG + seg*8);
        }
    };

    // ---- A smem loader (plain LDG/STS), nrows = 128 or 64 ----
    auto load_A = [&](const __nv_bfloat16* srcHi, const __nv_bfloat16* srcLo, int niter) {
        for (int i = 0; i < niter; i++) {
            int idx = tid + i*512;
            int row = idx >> 5, seg = idx & 31;
            uint32_t dst = (uint32_t)row*512 + (uint32_t)((seg ^ (row & 7))*16);
            *(uint4*)(smem + SM_AHI + dst) = *(const uint4*)(srcHi + (size_t)row*ND + seg*8);
            *(uint4*)(smem + SM_ALO + dst) = *(const uint4*)(srcLo + (size_t)row*ND + seg*8);
        }
    };

    int cload = 0;
    #pragma unroll
    for (int i = 0; i < 3; i++) { load_chunk(cload); CP_COMMIT(); cload++; }

    // ---------- phase 0: g_dek[row][s] = dot(enc_s, keys_row) (overlaps prefetch) ----
    {
        int r = tid >> 2, part = tid & 3;
        int grow = rowBase + r, b = grow >> 6;
        float4 ky[16];
        const float4* kp = (const float4*)(keys + (size_t)grow*ND + part*64);
        #pragma unroll
        for (int i = 0; i < 16; i++) ky[i] = kp[i];
        for (int s = 0; s < NS; s++) {
            const float4* ep = (const float4*)(g_enc + ((size_t)b*NS + s)*ND + part*64);
            float d = 0.f;
            #pragma unroll
            for (int i = 0; i < 16; i++) {
                float4 e = ep[i];
                d += ky[i].x*e.x + ky[i].y*e.y + ky[i].z*e.z + ky[i].w*e.w;
            }
            d += __shfl_xor_sync(0xffffffffu, d, 1);
            d += __shfl_xor_sync(0xffffffffu, d, 2);
            if (part == 0) g_dek[(size_t)grow*NS + s] = d;
        }
        if (tid < 128) gn[tid] = 0.f;
    }

    // ---- per-lane constants ----
    const int lane7 = lane & 7;
    const int sel2  = lane >> 4;
    const uint32_t arow = (uint32_t)(warp_m*32 + ((lane >> 3) & 1)*8 + lane7) * 512;
    const uint32_t boff4 = (uint32_t)(((lane >> 4)*8 + lane7)*80 + ((lane >> 3) & 1)*16);
    const int r7 = (lane >> 2) & 7;
    const uint32_t ebyte = (uint32_t)((lane & 3)*4);

    float acc[2][8][4];
    uint32_t ahc[2][8];                   // A-hi fragments carried even->odd chunk
    auto zero_acc = [&]() {
        #pragma unroll
        for (int mt = 0; mt < 2; mt++)
            #pragma unroll
            for (int nt = 0; nt < 8; nt++)
                #pragma unroll
                for (int q = 0; q < 4; q++) acc[mt][nt][q] = 0.f;
    };

    auto compute = [&](int c) {
        const int q = c & 15;
        const int kkidx = q >> 1;
        const bool isHi = !(q & 1);
        uint32_t bB = sb + SM_RING + (uint32_t)(c & 3)*STG + (warp_n*64)*80 + boff4;
        const int kseg0 = kkidx*4 + sel2;
        #pragma unroll
        for (int k2 = 0; k2 < 2; ++k2) {
            const uint32_t kb = (uint32_t)k2*32;
            uint32_t bq[16];
            #pragma unroll
            for (int np = 0; np < 4; np++) ldsm_x4(&bq[np*4], bB + np*1280 + kb);
            if (isHi) {
                const uint32_t seg = (uint32_t)((kseg0 + k2*2) ^ lane7) * 16;
                uint32_t aHa = sb + SM_AHI + arow + seg;
                ldsm_x4(&ahc[k2][0], aHa);
                ldsm_x4(&ahc[k2][4], aHa + 8192);
                #pragma unroll
                for (int np = 0; np < 4; np++) {
                    mma_bf16(acc[0][2*np],   &ahc[k2][0], &bq[np*4]);
                    mma_bf16(acc[0][2*np+1], &ahc[k2][0], &bq[np*4+2]);
                    mma_bf16(acc[1][2*np],   &ahc[k2][4], &bq[np*4]);
                    mma_bf16(acc[1][2*np+1], &ahc[k2][4], &bq[np*4+2]);
                }
                uint32_t aLa = sb + SM_ALO + arow + seg;
                uint32_t al[8];
                ldsm_x4(al,     aLa);
                ldsm_x4(al + 4, aLa + 8192);
                #pragma unroll
                for (int np = 0; np < 4; np++) {
                    mma_bf16(acc[0][2*np],   al,     &bq[np*4]);
                    mma_bf16(acc[0][2*np+1], al,     &bq[np*4+2]);
                    mma_bf16(acc[1][2*np],   al + 4, &bq[np*4]);
                    mma_bf16(acc[1][2*np+1], al + 4, &bq[np*4+2]);
                }
            } else {
                #pragma unroll
                for (int np = 0; np < 4; np++) {
                    mma_bf16(acc[0][2*np],   &ahc[k2][0], &bq[np*4]);
                    mma_bf16(acc[0][2*np+1], &ahc[k2][0], &bq[np*4+2]);
                    mma_bf16(acc[1][2*np],   &ahc[k2][4], &bq[np*4]);
                    mma_bf16(acc[1][2*np+1], &ahc[k2][4], &bq[np*4+2]);
                }
            }
        }
    };

    auto run16 = [&](int c0) {
        for (int i = 0; i < 16; ++i) {
            const int c = c0 + i;
            const int pend = cload - 1 - c;
            if (pend >= 2) CP_WAIT2(); else if (pend == 1) CP_WAIT1(); else CP_WAIT0();
            __syncthreads();
            if (cload < CTOT) { load_chunk(cload); CP_COMMIT(); cload++; }
            compute(c);
        }
    };

    // ---------- phase 1: kV = keys @ V for this CTA's 128 rows ----------
    load_A(g_kyhi + (size_t)rowBase*ND, g_kylo + (size_t)rowBase*ND, 8);
    __syncthreads();
    zero_acc();
    run16(0);
    __syncthreads();
    #pragma unroll
    for (int mt = 0; mt < 2; mt++) {
        int rA = warp_m*32 + mt*16 + (lane >> 2);
        int rB = rA + 8;
        size_t gOA = (size_t)(rowBase + rA)*ND;
        size_t gOB = (size_t)(rowBase + rB)*ND;
        #pragma unroll
        for (int nt = 0; nt < 8; nt++) {
            int col = warp_n*64 + nt*8 + 2*(lane & 3);
            *(float2*)(g_kV + gOA + col) = make_float2(acc[mt][nt][0], acc[mt][nt][1]);
            *(float2*)(g_kV + gOB + col) = make_float2(acc[mt][nt][2], acc[mt][nt][3]);
        }
    }

    // ---------- phase 2: eW = enc @ W for this CTA's 64 enc rows ----------
    load_A(g_enhi + (size_t)(bA0*32)*ND, g_enlo + (size_t)(bA0*32)*ND, 4);
    __syncthreads();
    zero_acc();
    run16(16);
    __syncthreads();
    if (warp_m < 2) {
        #pragma unroll
        for (int mt = 0; mt < 2; mt++) {
            int rA = warp_m*32 + mt*16 + (lane >> 2);
            int rB = rA + 8;
            size_t gOA = (size_t)(bA0*32 + rA)*ND;
            size_t gOB = (size_t)(bA0*32 + rB)*ND;
            #pragma unroll
            for (int nt = 0; nt < 8; nt++) {
                int col = warp_n*64 + nt*8 + 2*(lane & 3);
                *(float2*)(g_eW + gOA + col) = make_float2(acc[mt][nt][0], acc[mt][nt][1]);
                *(float2*)(g_eW + gOB + col) = make_float2(acc[mt][nt][2], acc[mt][nt][3]);
            }
        }
    }

    // ---------- phase 3: the 32-step recurrence ----------
    for (int s = 0; s < NS; ++s) {
        const bool first = (s == 0);
        const bool last  = (s == NS - 1);
        __syncthreads();
        if (tid < 128) {
            int grow = rowBase + tid;
            int b = grow >> 6;
            gs[tid]   = 1.f / (1.f + expf(-(gn[tid] + g_dek[(size_t)grow*NS + s])));
            acts[tid] = g_act[b*NS + s];
        }

        zero_acc();

        if (!first) {
            run16(32 + (s - 1)*16);
        } else {
            __syncthreads();
        }

        // ---------- epilogue pass 1 (h state from persistent smem) ----------
        const int sn = (s + 1 < NS) ? s + 1 : NS - 1;
        #pragma unroll
        for (int mt = 0; mt < 2; mt++) {
            int rA = warp_m*32 + mt*16 + (lane >> 2);
            int rB = rA + 8;
            int gA = rowBase + rA, gB = rowBase + rB;
            int bA = gA >> 6;
            const float* kvA = g_kV + (size_t)gA*ND;
            const float* kvB = g_kV + (size_t)gB*ND;
            const float* ewR = g_eW  + ((size_t)bA*NS + s )*ND;
            const float* enN = g_enc + ((size_t)bA*NS + sn)*ND;
            float gateA = gs[rA], gateB = gs[rB];
            float sA = 0.f, sB = 0.f;
            float dVA = 0.f, dVB = 0.f, dHA = 0.f, dHB = 0.f;
            #pragma unroll
            for (int nt = 0; nt < 8; nt++) {
                int col = warp_n*64 + nt*8 + 2*(lane & 3);
                const uint32_t seg = (uint32_t)((warp_n*8 + nt) ^ r7) * 16;
                float2 en = *(const float2*)(enN + col);
                float2 ew = *(const float2*)(ewR + col);
                float2 kv, ho;
                kv = *(const float2*)(kvA + col);
                if (first) ho = make_float2(0.f, 0.f);
                else {
                    uint32_t offA = (uint32_t)rA*512 + seg + ebyte;
                    __nv_bfloat162 hb = *(__nv_bfloat162*)(smem + SM_AHI + offA);
                    __nv_bfloat162 lb = *(__nv_bfloat162*)(smem + SM_ALO + offA);
                    ho = make_float2(__bfloat162float(hb.x) + __bfloat162float(lb.x),
                                     __bfloat162float(hb.y) + __bfloat162float(lb.y));
                }
                float v0 = fmaxf(acc[mt][nt][0] + kv.x + ew.x, 0.f);
                float v1 = fmaxf(acc[mt][nt][1] + kv.y + ew.y, 0.f);
                float h0 = ho.x + gateA*v0, h1 = ho.y + gateA*v1;
                acc[mt][nt][0] = h0; acc[mt][nt][1] = h1;
                sA  += h0*h0 + h1*h1;
                dVA += en.x*h0 + en.y*h1;
                dHA += en.x*ho.x + en.y*ho.y;
                kv = *(const float2*)(kvB + col);
                if (first) ho = make_float2(0.f, 0.f);
                else {
                    uint32_t offB = (uint32_t)rB*512 + seg + ebyte;
                    __nv_bfloat162 hb = *(__nv_bfloat162*)(smem + SM_AHI + offB);
                    __nv_bfloat162 lb = *(__nv_bfloat162*)(smem + SM_ALO + offB);
                    ho = make_float2(__bfloat162float(hb.x) + __bfloat162float(lb.x),
                                     __bfloat162float(hb.y) + __bfloat162float(lb.y));
                }
                float w0 = fmaxf(acc[mt][nt][2] + kv.x + ew.x, 0.f);
                float w1 = fmaxf(acc[mt][nt][3] + kv.y + ew.y, 0.f);
                float h2 = ho.x + gateB*w0, h3 = ho.y + gateB*w1;
                acc[mt][nt][2] = h2; acc[mt][nt][3] = h3;
                sB  += h2*h2 + h3*h3;
                dVB += en.x*h2 + en.y*h3;
                dHB += en.x*ho.x + en.y*ho.y;
            }
            #pragma unroll
            for (int o = 1; o <= 2; o <<= 1) {
                sA  += __shfl_xor_sync(0xffffffffu, sA,  o);
                sB  += __shfl_xor_sync(0xffffffffu, sB,  o);
                dVA += __shfl_xor_sync(0xffffffffu, dVA, o);
                dVB += __shfl_xor_sync(0xffffffffu, dVB, o);
                dHA += __shfl_xor_sync(0xffffffffu, dHA, o);
                dHB += __shfl_xor_sync(0xffffffffu, dHB, o);
            }
            if ((lane & 3) == 0) {
                float* rs4 = (float*)(smem + SM_RS4) + warp_n*128;
                float* dv4 = (float*)(smem + SM_DV4) + warp_n*128;
                float* dh4 = (float*)(smem + SM_DH4) + warp_n*128;
                rs4[rA] = sA;  rs4[rB] = sB;
                dv4[rA] = dVA; dv4[rB] = dVB;
                dh4[rA] = dHA; dh4[rB] = dHB;
            }
        }
        __syncthreads();
        if (tid < 128) {
            const float* rs4 = (const float*)(smem + SM_RS4);
            const float* dv4 = (const float*)(smem + SM_DV4);
            const float* dh4 = (const float*)(smem + SM_DH4);
            float sq = rs4[tid] + rs4[128+tid] + rs4[256+tid] + rs4[384+tid];
            float dv = dv4[tid] + dv4[128+tid] + dv4[256+tid] + dv4[384+tid];
            float dh = dh4[tid] + dh4[128+tid] + dh4[256+tid] + dh4[384+tid];
            float r = rsqrtf(fmaxf(sq, 1e-12f));
            rs[tid] = r;
            gn[tid] = acts[tid] ? dv*r : dh;
        }
        __syncthreads();

        // ---------- epilogue pass 2: normalize + write smem hi/lo (+h gmem at last) --
        #pragma unroll
        for (int mt = 0; mt < 2; mt++) {
            int rA = warp_m*32 + mt*16 + (lane >> 2);
            int rB = rA + 8;
            float rn2[2] = { rs[rA], rs[rB] };
            int   ac2[2] = { acts[rA], acts[rB] };
            int   rr2[2] = { rA, rB };
            #pragma unroll
            for (int half = 0; half < 2; half++) {
                float rn = rn2[half]; int aa = ac2[half]; int row = rr2[half];
                size_t gO = (size_t)(rowBase + row)*ND;
                #pragma unroll
                for (int nt = 0; nt < 8; nt++) {
                    int col = warp_n*64 + nt*8 + 2*(lane & 3);
                    uint32_t off = (uint32_t)row*512 + (uint32_t)((warp_n*8 + nt) ^ r7)*16 + ebyte;
                    float a0 = acc[mt][nt][half*2], a1 = acc[mt][nt][half*2+1];
                    if (aa || first) {
                        float v0 = aa ? a0*rn : 0.f;
                        float v1 = aa ? a1*rn : 0.f;
                        __nv_bfloat16 h0 = __float2bfloat16(v0), h1 = __float2bfloat16(v1);
                        *(__nv_bfloat162*)(smem + SM_AHI + off) = __nv_bfloat162(h0, h1);
                        *(__nv_bfloat162*)(smem + SM_ALO + off) = __nv_bfloat162(
                            __float2bfloat16(v0 - __bfloat162float(h0)),
                            __float2bfloat16(v1 - __bfloat162float(h1)));
                        if (last) *(float2*)(h + gO + col) = make_float2(v0, v1);
                    } else if (last) {
                        __nv_bfloat162 hb = *(__nv_bfloat162*)(smem + SM_AHI + off);
                        __nv_bfloat162 lb = *(__nv_bfloat162*)(smem + SM_ALO + off);
                        *(float2*)(h + gO + col) = make_float2(
                            __bfloat162float(hb.x) + __bfloat162float(lb.x),
                            __bfloat162float(hb.y) + __bfloat162float(lb.y));
                    }
                }
            }
        }
    }
}

// ===================== launch =====================
extern "C" void kernel_launch(void* const* d_in, const int* in_sizes, int n_in,
                              void* d_out, int out_size) {
    const int*   tok  = (const int*)  d_in[0];
    const float* mask = (const float*)d_in[1];
    const float* keys = (const float*)d_in[2];
    const float* emb  = (const float*)d_in[3];
    const float* U    = (const float*)d_in[4];
    const float* V    = (const float*)d_in[5];
    const float* W    = (const float*)d_in[6];
    float* h = (float*)d_out;

    cudaFuncSetAttribute(steps_kernel, cudaFuncAttributeMaxDynamicSharedMemorySize, SMEM_STEPS);

    encode_kernel<<<NB*NS, 256>>>(tok, mask, emb);
    prep_bt_all<<<3*ND, ND>>>(U, V, W);
    split_kernel<<<(NB*NE*ND)/256, 256>>>(keys);
    steps_kernel<<<128, 512, SMEM_STEPS>>>(keys, h);
}